// round 14
// baseline (speedup 1.0000x reference)
#include <cuda_runtime.h>
#include <math.h>

#define FLOW_SZ 1048576       // 2*2*512*512

// ---- packed weights (filled by upsample kernel's prep blocks) ----
// Layout: pair pr, lane l -> float4(w[c][2l], w[c][2l+1], w[c+1][2l], w[c+1][2l+1]), c=2*local_pair
// Regions (in pairs): W1 [0,42) (rows 80..83 zero-padded), W2 [42,74), WQ [74,106),
// WV [106,170), WP1 [170,202), WP2 [202,234), F1 [234,266), F2 [266,298)
#define OFF_W1  0
#define OFF_W2  (42 * 32)
#define OFF_WQ  (74 * 32)
#define OFF_WV  (106 * 32)
#define OFF_WP1 (170 * 32)
#define OFF_WP2 (202 * 32)
#define OFF_F1  (234 * 32)
#define OFF_F2  (266 * 32)
#define WPK_TOTAL (298 * 32)   // 9536 float4

__device__ __align__(16) float4 g_wpk[WPK_TOTAL];
__device__ __align__(16) float g_wk_t[64 * 128];   // g_wk_t[d*128+c] = wk[c*64+d]

__device__ __forceinline__ float gelu_exact(float x) {
    return 0.5f * x * (1.0f + erff(x * 0.70710678118654752f));
}

__device__ __forceinline__ float samp_map(const float* __restrict__ p, int ix, int iy) {
    if ((unsigned)ix < 64u && (unsigned)iy < 64u) return p[iy * 64 + ix];
    return 0.0f;
}

__device__ __forceinline__ float4 fma4(float s, float4 a, float4 b) {
    return make_float4(fmaf(s, a.x, b.x), fmaf(s, a.y, b.y),
                       fmaf(s, a.z, b.z), fmaf(s, a.w, b.w));
}

__device__ __forceinline__ float posenc(float cx, float cy, int o) {
    int r = o >> 4, f = o & 15;
    float base = (r < 2) ? cx : cy;
    float ang = 3.14f * base * (float)f / 200.0f;
    return ((r & 1) == 0) ? __sinf(ang) : __cosf(ang);
}

// Dual-token matmul on packed weights: out[o] += sum_c act[t][c]*w[c][o],
// o0=2*lane, o1=2*lane+1. PAIRS must be even. 2 LDG.128 + 2 LDS.128 + 16 FFMA
// per 4 rows per 2 tokens.
template <int PAIRS>
__device__ __forceinline__ void mm2p(const float* a0, const float* a1,
                                     const float4* __restrict__ P, int l,
                                     float2& r0, float2& r1)
{
    P += l;
    #pragma unroll 4
    for (int p = 0; p < PAIRS; p += 2) {
        float4 x0 = *(const float4*)(a0 + 2 * p);
        float4 x1 = *(const float4*)(a1 + 2 * p);
        float4 wA = P[p * 32];
        float4 wB = P[(p + 1) * 32];
        r0.x = fmaf(x0.x, wA.x, r0.x); r0.y = fmaf(x0.x, wA.y, r0.y);
        r0.x = fmaf(x0.y, wA.z, r0.x); r0.y = fmaf(x0.y, wA.w, r0.y);
        r1.x = fmaf(x1.x, wA.x, r1.x); r1.y = fmaf(x1.x, wA.y, r1.y);
        r1.x = fmaf(x1.y, wA.z, r1.x); r1.y = fmaf(x1.y, wA.w, r1.y);
        r0.x = fmaf(x0.z, wB.x, r0.x); r0.y = fmaf(x0.z, wB.y, r0.y);
        r0.x = fmaf(x0.w, wB.z, r0.x); r0.y = fmaf(x0.w, wB.w, r0.y);
        r1.x = fmaf(x1.z, wB.x, r1.x); r1.y = fmaf(x1.z, wB.y, r1.y);
        r1.x = fmaf(x1.w, wB.z, r1.x); r1.y = fmaf(x1.w, wB.w, r1.y);
    }
}

// Per-warp shared state for 2 tokens.
struct __align__(16) WarpSmem {
    float u[2][1056];     // 8 x 132 rows of u[h][c] (written in phase 8)
    float corr[2][88];    // 81 correlation values; [81..87] zeroed
    float attn[2][64];    // softmaxed attention
    float qlin[2][64];
    float A[2][64];       // gelu(fte1) -> attn_out -> ffn hidden
    float B[2][64];       // normed (+enc) vectors
    float sh[2][64];      // short (residual)
    float xs[2][64];      // final
};

// Reduce v[8] (partial scores for j=0..7) across lanes -> score for j=(l>>2)&7.
__device__ __forceinline__ float score_reduce(float* v, int l) {
    bool up = (l & 16) != 0;
    #pragma unroll
    for (int i = 0; i < 4; ++i) {
        float send = up ? v[i] : v[i + 4];
        float recv = __shfl_xor_sync(0xffffffffu, send, 16);
        v[i] = (up ? v[i + 4] : v[i]) + recv;
    }
    up = (l & 8) != 0;
    #pragma unroll
    for (int i = 0; i < 2; ++i) {
        float send = up ? v[i] : v[i + 2];
        float recv = __shfl_xor_sync(0xffffffffu, send, 8);
        v[i] = (up ? v[i + 2] : v[i]) + recv;
    }
    up = (l & 4) != 0;
    {
        float send = up ? v[0] : v[1];
        float recv = __shfl_xor_sync(0xffffffffu, send, 4);
        v[0] = (up ? v[1] : v[0]) + recv;
    }
    v[0] += __shfl_xor_sync(0xffffffffu, v[0], 2);
    v[0] += __shfl_xor_sync(0xffffffffu, v[0], 1);
    return v[0];
}

__device__ __forceinline__ float softmax_j(float s, int l) {
    float mx = s;
    mx = fmaxf(mx, __shfl_xor_sync(0xffffffffu, mx, 4));
    mx = fmaxf(mx, __shfl_xor_sync(0xffffffffu, mx, 8));
    mx = fmaxf(mx, __shfl_xor_sync(0xffffffffu, mx, 16));
    float e = __expf(s - mx);
    float sum = e;
    sum += __shfl_xor_sync(0xffffffffu, sum, 4);
    sum += __shfl_xor_sync(0xffffffffu, sum, 8);
    sum += __shfl_xor_sync(0xffffffffu, sum, 16);
    return e / sum;
}

__global__ __launch_bounds__(64, 9) void decoder_kernel(
    const float* __restrict__ cost_maps,
    const float* __restrict__ cost_memory,
    const float* __restrict__ coords1,
    const float* __restrict__ fte_b1,
    const float* __restrict__ fte_b2,
    const float* __restrict__ ln1_g, const float* __restrict__ ln1_b,
    const float* __restrict__ ln2_g, const float* __restrict__ ln2_b,
    const float* __restrict__ bq,  const float* __restrict__ bv,
    const float* __restrict__ bp,
    const float* __restrict__ fb1, const float* __restrict__ fb2,
    float* __restrict__ out)
{
    __shared__ WarpSmem ts[2];
    const int warp = threadIdx.x >> 5;
    const int l = threadIdx.x & 31;
    const int n0 = blockIdx.x * 4 + warp * 2;   // tokens n0, n0+1
    WarpSmem& S = ts[warp];

    const int b = n0 >> 12;
    const int pix0 = n0 & 4095;
    const float cx0 = coords1[b * 8192 + pix0];
    const float cy0 = coords1[b * 8192 + 4096 + pix0];
    const float cx1 = coords1[b * 8192 + pix0 + 1];
    const float cy1 = coords1[b * 8192 + 4096 + pix0 + 1];
    const int o0 = 2 * l, o1 = 2 * l + 1;

    // ---- phase 1: bilinear correlation sampling (si fast across lanes) ----
    #pragma unroll
    for (int t = 0; t < 2; ++t) {
        const float* cmap = cost_maps + (size_t)(n0 + t) * 4096;
        const float cx = t ? cx1 : cx0;
        const float cy = t ? cy1 : cy0;
        for (int ss = l; ss < 81; ss += 32) {
            int si = ss % 9, sj = ss / 9;
            float px = cx + (float)(si - 4);
            float py = cy + (float)(sj - 4);
            float fx0 = floorf(px), fy0 = floorf(py);
            float wx = px - fx0, wy = py - fy0;
            int ix = (int)fx0, iy = (int)fy0;
            float v00 = samp_map(cmap, ix,     iy);
            float v10 = samp_map(cmap, ix + 1, iy);
            float v01 = samp_map(cmap, ix,     iy + 1);
            float v11 = samp_map(cmap, ix + 1, iy + 1);
            S.corr[t][si * 9 + sj] =
                  v00 * (1.f - wx) * (1.f - wy) + v10 * wx * (1.f - wy)
                + v01 * (1.f - wx) * wy         + v11 * wx * wy;
        }
        if (l < 7) S.corr[t][81 + l] = 0.f;   // zero pad rows 81..87
    }
    __syncwarp();

    // ---- phase 2: FTE1 = gelu(corr @ W1 + b1)  (rows 0..83, 81+ zero) ----
    {
        float2 bb = *(const float2*)(fte_b1 + o0);
        float2 r0 = bb, r1 = bb;
        mm2p<42>(S.corr[0], S.corr[1], g_wpk + OFF_W1, l, r0, r1);
        *(float2*)&S.A[0][o0] = make_float2(gelu_exact(r0.x), gelu_exact(r0.y));
        *(float2*)&S.A[1][o0] = make_float2(gelu_exact(r1.x), gelu_exact(r1.y));
    }
    __syncwarp();

    // ---- phase 3: query = A @ W2 + b2 (= short) ----
    float2 q0, q1;
    {
        float2 bb = *(const float2*)(fte_b2 + o0);
        q0 = bb; q1 = bb;
        mm2p<32>(S.A[0], S.A[1], g_wpk + OFF_W2, l, q0, q1);
        *(float2*)&S.sh[0][o0] = q0;
        *(float2*)&S.sh[1][o0] = q1;
    }

    // ---- phase 4: layernorm1 + positional encoding ----
    {
        float s0 = q0.x + q0.y, s1 = q1.x + q1.y;
        #pragma unroll
        for (int off = 16; off; off >>= 1) {
            s0 += __shfl_xor_sync(0xffffffffu, s0, off);
            s1 += __shfl_xor_sync(0xffffffffu, s1, off);
        }
        float m0 = s0 * (1.f / 64.f), m1 = s1 * (1.f / 64.f);
        float d00 = q0.x - m0, d01 = q0.y - m0;
        float d10 = q1.x - m1, d11 = q1.y - m1;
        float v0 = d00 * d00 + d01 * d01, v1 = d10 * d10 + d11 * d11;
        #pragma unroll
        for (int off = 16; off; off >>= 1) {
            v0 += __shfl_xor_sync(0xffffffffu, v0, off);
            v1 += __shfl_xor_sync(0xffffffffu, v1, off);
        }
        float i0 = rsqrtf(v0 * (1.f / 64.f) + 1e-5f);
        float i1 = rsqrtf(v1 * (1.f / 64.f) + 1e-5f);
        float2 g2 = *(const float2*)(ln1_g + o0);
        float2 b2v = *(const float2*)(ln1_b + o0);
        float e00 = posenc(cx0, cy0, o0), e01 = posenc(cx0, cy0, o1);
        float e10 = posenc(cx1, cy1, o0), e11 = posenc(cx1, cy1, o1);
        *(float2*)&S.B[0][o0] = make_float2(d00 * i0 * g2.x + b2v.x + e00,
                                            d01 * i0 * g2.y + b2v.y + e01);
        *(float2*)&S.B[1][o0] = make_float2(d10 * i1 * g2.x + b2v.x + e10,
                                            d11 * i1 * g2.y + b2v.y + e11);
    }
    __syncwarp();

    // ---- phase 5: qlin = B @ wq + bq ----
    {
        float2 bb = *(const float2*)(bq + o0);
        float2 r0 = bb, r1 = bb;
        mm2p<32>(S.B[0], S.B[1], g_wpk + OFF_WQ, l, r0, r1);
        *(float2*)&S.qlin[0][o0] = r0;
        *(float2*)&S.qlin[1][o0] = r1;
    }
    __syncwarp();

    // ---- phases 6-8 fused, one token at a time; cm fragments from gmem ----
    const float4* wk4 = (const float4*)g_wk_t;
    const float scale = 0.35355339059327373f;
    #pragma unroll
    for (int t = 0; t < 2; ++t) {
        float4 cmf[8];
        const float* cmbase = cost_memory + (size_t)(n0 + t) * 1024 + 4 * l;
        #pragma unroll
        for (int j = 0; j < 8; ++j)
            cmf[j] = *(const float4*)(cmbase + j * 128);

        #pragma unroll
        for (int h = 0; h < 8; ++h) {
            float qv[8];
            *(float4*)&qv[0] = *(const float4*)&S.qlin[t][h * 8];
            *(float4*)&qv[4] = *(const float4*)&S.qlin[t][h * 8 + 4];
            float4 tf = make_float4(0.f, 0.f, 0.f, 0.f);
            #pragma unroll
            for (int e = 0; e < 8; ++e)
                tf = fma4(qv[e], wk4[(h * 8 + e) * 32 + l], tf);
            float v[8];
            #pragma unroll
            for (int j = 0; j < 8; ++j)
                v[j] = fmaf(tf.x, cmf[j].x, fmaf(tf.y, cmf[j].y,
                       fmaf(tf.z, cmf[j].z, tf.w * cmf[j].w)));
            float s = score_reduce(v, l) * scale;
            float a = softmax_j(s, l);
            if ((l & 3) == 0)
                S.attn[t][h * 8 + ((l >> 2) & 7)] = a;
        }
        __syncwarp();   // attn[t] visible

        float4 ua[8];
        #pragma unroll
        for (int h = 0; h < 8; ++h) ua[h] = make_float4(0.f, 0.f, 0.f, 0.f);
        #pragma unroll
        for (int j = 0; j < 8; ++j) {
            float4 m = cmf[j];
            #pragma unroll
            for (int h = 0; h < 8; ++h)
                ua[h] = fma4(S.attn[t][h * 8 + j], m, ua[h]);
        }
        #pragma unroll
        for (int h = 0; h < 8; ++h)
            *(float4*)&S.u[t][h * 132 + 4 * l] = ua[h];
    }
    __syncwarp();

    // ---- phase 9: out = u @ wv + bv ----
    {
        float2 bb = *(const float2*)(bv + o0);
        float2 r0 = bb, r1 = bb;
        const int h = l >> 2;   // head of both o0 and o1
        mm2p<64>(&S.u[0][h * 132], &S.u[1][h * 132], g_wpk + OFF_WV, l, r0, r1);
        *(float2*)&S.A[0][o0] = r0;
        *(float2*)&S.A[1][o0] = r1;
    }
    __syncwarp();

    // ---- phase 10: x = concat(out, short) @ wp + bp + short ----
    float2 x0, x1;
    {
        float2 bb = *(const float2*)(bp + o0);
        x0 = bb; x1 = bb;
        mm2p<32>(S.A[0], S.A[1], g_wpk + OFF_WP1, l, x0, x1);
        mm2p<32>(S.sh[0], S.sh[1], g_wpk + OFF_WP2, l, x0, x1);
        float2 sh0 = *(const float2*)&S.sh[0][o0];
        float2 sh1 = *(const float2*)&S.sh[1][o0];
        x0.x += sh0.x; x0.y += sh0.y;
        x1.x += sh1.x; x1.y += sh1.y;
    }

    // ---- phase 11: layernorm2 ----
    {
        float s0 = x0.x + x0.y, s1 = x1.x + x1.y;
        #pragma unroll
        for (int off = 16; off; off >>= 1) {
            s0 += __shfl_xor_sync(0xffffffffu, s0, off);
            s1 += __shfl_xor_sync(0xffffffffu, s1, off);
        }
        float m0 = s0 * (1.f / 64.f), m1 = s1 * (1.f / 64.f);
        float d00 = x0.x - m0, d01 = x0.y - m0;
        float d10 = x1.x - m1, d11 = x1.y - m1;
        float v0 = d00 * d00 + d01 * d01, v1 = d10 * d10 + d11 * d11;
        #pragma unroll
        for (int off = 16; off; off >>= 1) {
            v0 += __shfl_xor_sync(0xffffffffu, v0, off);
            v1 += __shfl_xor_sync(0xffffffffu, v1, off);
        }
        float i0 = rsqrtf(v0 * (1.f / 64.f) + 1e-5f);
        float i1 = rsqrtf(v1 * (1.f / 64.f) + 1e-5f);
        float2 g2 = *(const float2*)(ln2_g + o0);
        float2 b2v = *(const float2*)(ln2_b + o0);
        *(float2*)&S.B[0][o0] = make_float2(d00 * i0 * g2.x + b2v.x,
                                            d01 * i0 * g2.y + b2v.y);
        *(float2*)&S.B[1][o0] = make_float2(d10 * i1 * g2.x + b2v.x,
                                            d11 * i1 * g2.y + b2v.y);
    }
    __syncwarp();

    // ---- phase 12: FFN hidden ----
    {
        float2 bb = *(const float2*)(fb1 + o0);
        float2 r0 = bb, r1 = bb;
        mm2p<32>(S.B[0], S.B[1], g_wpk + OFF_F1, l, r0, r1);
        *(float2*)&S.A[0][o0] = make_float2(gelu_exact(r0.x), gelu_exact(r0.y));
        *(float2*)&S.A[1][o0] = make_float2(gelu_exact(r1.x), gelu_exact(r1.y));
    }
    __syncwarp();

    // ---- phase 13: FFN out + residual ----
    {
        float2 bb = *(const float2*)(fb2 + o0);
        float2 r0 = bb, r1 = bb;
        mm2p<32>(S.A[0], S.A[1], g_wpk + OFF_F2, l, r0, r1);
        *(float2*)&S.xs[0][o0] = make_float2(x0.x + r0.x, x0.y + r0.y);
        *(float2*)&S.xs[1][o0] = make_float2(x1.x + r1.x, x1.y + r1.y);
    }

    // ---- phase 14: block-staged transposed writeout (STG.128) ----
    __syncthreads();
    {
        int nb = blockIdx.x * 4;
        int bb = nb >> 12;
        int px = nb & 4095;
        float* cg = out + FLOW_SZ + (size_t)bb * 64 * 4096 + px;
        int o = threadIdx.x;   // 0..63
        float4 v = make_float4(ts[0].xs[0][o], ts[0].xs[1][o],
                               ts[1].xs[0][o], ts[1].xs[1][o]);
        *(float4*)(cg + (size_t)o * 4096) = v;
    }
}

// ============================================================================
// Convex upsampling, 16 pixels per block. Blocks 0..37 pack the matmul
// weights into g_wpk; blocks 38..69 transpose wk into g_wk_t.
// ============================================================================
__global__ __launch_bounds__(256) void upsample_kernel(
    const float* __restrict__ coords1,
    const float* __restrict__ up_mask,
    const float* __restrict__ fte_w1,
    const float* __restrict__ fte_w2,
    const float* __restrict__ wq,
    const float* __restrict__ wk,
    const float* __restrict__ wv,
    const float* __restrict__ wp,
    const float* __restrict__ fw1,
    const float* __restrict__ fw2,
    float* __restrict__ out)
{
    extern __shared__ float dyn[];
    const int PAD = 20;            // slab row stride in floats (float4-aligned)
    float* slab = dyn;             // 576 * PAD
    float* fl   = dyn + 576 * PAD; // 2 * 3 * 18

    int blk = blockIdx.x;
    int tid = threadIdx.x;

    if (blk < 38) {
        int i = blk * 256 + tid;      // float4 index into g_wpk
        if (i < WPK_TOTAL) {
            int pr = i >> 5, l = i & 31;
            int oA = 2 * l, oB = 2 * l + 1;
            float4 v;
            if (pr < 42) {
                int c = 2 * pr;
                v.x = (c < 81)     ? fte_w1[oA * 81 + c]     : 0.f;
                v.y = (c < 81)     ? fte_w1[oB * 81 + c]     : 0.f;
                v.z = (c + 1 < 81) ? fte_w1[oA * 81 + c + 1] : 0.f;
                v.w = (c + 1 < 81) ? fte_w1[oB * 81 + c + 1] : 0.f;
            } else if (pr < 74) {
                int c = 2 * (pr - 42);
                v = make_float4(fte_w2[oA * 64 + c], fte_w2[oB * 64 + c],
                                fte_w2[oA * 64 + c + 1], fte_w2[oB * 64 + c + 1]);
            } else if (pr < 106) {
                int c = 2 * (pr - 74);
                v = make_float4(wq[c * 64 + oA], wq[c * 64 + oB],
                                wq[(c + 1) * 64 + oA], wq[(c + 1) * 64 + oB]);
            } else if (pr < 170) {
                int c = 2 * (pr - 106);
                v = make_float4(wv[c * 64 + oA], wv[c * 64 + oB],
                                wv[(c + 1) * 64 + oA], wv[(c + 1) * 64 + oB]);
            } else if (pr < 234) {
                int c = 2 * (pr - 170);   // rows 0..127 of wp (WP1 then WP2)
                v = make_float4(wp[c * 64 + oA], wp[c * 64 + oB],
                                wp[(c + 1) * 64 + oA], wp[(c + 1) * 64 + oB]);
            } else if (pr < 266) {
                int c = 2 * (pr - 234);
                v = make_float4(fw1[c * 64 + oA], fw1[c * 64 + oB],
                                fw1[(c + 1) * 64 + oA], fw1[(c + 1) * 64 + oB]);
            } else {
                int c = 2 * (pr - 266);
                v = make_float4(fw2[c * 64 + oA], fw2[c * 64 + oB],
                                fw2[(c + 1) * 64 + oA], fw2[(c + 1) * 64 + oB]);
            }
            g_wpk[i] = v;
        }
    } else if (blk < 70) {
        int i = (blk - 38) * 256 + tid;   // [0, 8192)
        int d = i >> 7, c = i & 127;
        g_wk_t[i] = wk[c * 64 + d];
    }

    // 512 blocks: b (2) x y (64) x x-tile (4 of 16 px)
    const int b  = blk >> 8;           // 0..1
    const int r2 = blk & 255;
    const int y  = r2 >> 2;            // 0..63
    const int x0 = (r2 & 3) << 4;      // 0,16,32,48

    // load mask slab: 576 channels x 16 px = 4 float4 per channel
    const float* mbase = up_mask + (size_t)b * 576 * 4096 + y * 64 + x0;
    for (int idx = tid; idx < 576 * 4; idx += 256) {
        int ch = idx >> 2, k = idx & 3;
        *(float4*)&slab[ch * PAD + 4 * k] =
            *(const float4*)(mbase + (size_t)ch * 4096 + 4 * k);
    }
    // flow neighborhood: rows y-1..y+1, cols x0-1..x0+16 (18 wide), 2 comps
    for (int idx = tid; idx < 2 * 3 * 18; idx += 256) {
        int c = idx / 54, rr = idx % 54, r = rr / 18, cc = rr % 18;
        int yy = y + r - 1, xx = x0 + cc - 1;
        float v = 0.0f;
        if ((unsigned)yy < 64u && (unsigned)xx < 64u) {
            float coord = coords1[b * 8192 + c * 4096 + yy * 64 + xx];
            v = 8.0f * (coord - (float)(c == 0 ? xx : yy));
        }
        fl[c * 54 + r * 18 + cc] = v;
    }
    __syncthreads();

    // 1024 sites: site = i*128 + p*8 + j  (i sub-row, p pixel, j sub-col)
    float* ob0 = out + (size_t)b * 2 * 512 * 512 + (size_t)(8 * y) * 512 + x0 * 8;
    for (int it = 0; it < 4; ++it) {
        int site = it * 256 + tid;
        int i = site >> 7;
        int rr = site & 127;
        int p = rr >> 3, j = rr & 7;
        int ij = i * 8 + j;
        float w[9];
        float mx = -1e30f;
        #pragma unroll
        for (int kk = 0; kk < 9; ++kk) {
            w[kk] = slab[(kk * 64 + ij) * PAD + p];
            mx = fmaxf(mx, w[kk]);
        }
        float s = 0.f;
        #pragma unroll
        for (int kk = 0; kk < 9; ++kk) { w[kk] = __expf(w[kk] - mx); s += w[kk]; }
        float inv = 1.0f / s;
        float u0 = 0.f, u1 = 0.f;
        #pragma unroll
        for (int kk = 0; kk < 9; ++kk) {
            int dy = kk / 3, dx = kk - dy * 3;
            u0 = fmaf(w[kk], fl[0 * 54 + dy * 18 + p + dx], u0);
            u1 = fmaf(w[kk], fl[1 * 54 + dy * 18 + p + dx], u1);
        }
        float* o = ob0 + (size_t)i * 512 + p * 8 + j;
        o[0] = u0 * inv;
        o[512 * 512] = u1 * inv;
    }
}

extern "C" void kernel_launch(void* const* d_in, const int* in_sizes, int n_in,
                              void* d_out, int out_size) {
    const float* cost_maps   = (const float*)d_in[0];
    const float* cost_memory = (const float*)d_in[1];
    const float* coords1     = (const float*)d_in[2];
    const float* up_mask     = (const float*)d_in[3];
    const float* fte_w1      = (const float*)d_in[4];
    const float* fte_b1      = (const float*)d_in[5];
    const float* fte_w2      = (const float*)d_in[6];
    const float* fte_b2      = (const float*)d_in[7];
    const float* ln1_g       = (const float*)d_in[8];
    const float* ln1_b       = (const float*)d_in[9];
    const float* ln2_g       = (const float*)d_in[10];
    const float* ln2_b       = (const float*)d_in[11];
    const float* wq          = (const float*)d_in[12];
    const float* bq          = (const float*)d_in[13];
    const float* wk          = (const float*)d_in[14];
    const float* wv          = (const float*)d_in[16];
    const float* bv          = (const float*)d_in[17];
    const float* wp          = (const float*)d_in[18];
    const float* bp          = (const float*)d_in[19];
    const float* fw1         = (const float*)d_in[20];
    const float* fb1         = (const float*)d_in[21];
    const float* fw2         = (const float*)d_in[22];
    const float* fb2         = (const float*)d_in[23];
    float* out = (float*)d_out;

    const int smem_bytes = (576 * 20 + 2 * 3 * 18) * 4;   // 46,512 B
    cudaFuncSetAttribute(upsample_kernel,
                         cudaFuncAttributeMaxDynamicSharedMemorySize, smem_bytes);

    upsample_kernel<<<512, 256, smem_bytes>>>(coords1, up_mask, fte_w1, fte_w2,
                                              wq, wk, wv, wp, fw1, fw2, out);
    decoder_kernel<<<2048, 64>>>(cost_maps, cost_memory, coords1,
                                 fte_b1, fte_b2,
                                 ln1_g, ln1_b, ln2_g, ln2_b,
                                 bq, bv, bp, fb1, fb2, out);
}

// round 15
// speedup vs baseline: 1.1466x; 1.1466x over previous
#include <cuda_runtime.h>
#include <math.h>

#define FLOW_SZ 1048576       // 2*2*512*512

// ---- packed weights (filled by upsample kernel's prep blocks) ----
// Layout: pair pr, lane l -> float4(w[c][2l], w[c][2l+1], w[c+1][2l], w[c+1][2l+1])
// Regions (in pairs): W1 [0,42) (rows 80..83 zero-padded), W2 [42,74), WQ [74,106),
// WV [106,170), WP1 [170,202), WP2 [202,234), F1 [234,266), F2 [266,298)
#define OFF_W1  0
#define OFF_W2  (42 * 32)
#define OFF_WQ  (74 * 32)
#define OFF_WV  (106 * 32)
#define OFF_WP1 (170 * 32)
#define OFF_WP2 (202 * 32)
#define OFF_F1  (234 * 32)
#define OFF_F2  (266 * 32)
#define WPK_TOTAL (298 * 32)   // 9536 float4

__device__ __align__(16) float4 g_wpk[WPK_TOTAL];
__device__ __align__(16) float g_wk_t[64 * 128];   // g_wk_t[d*128+c] = wk[c*64+d]

__device__ __forceinline__ float gelu_exact(float x) {
    return 0.5f * x * (1.0f + erff(x * 0.70710678118654752f));
}

__device__ __forceinline__ float samp_map(const float* __restrict__ p, int ix, int iy) {
    if ((unsigned)ix < 64u && (unsigned)iy < 64u) return p[iy * 64 + ix];
    return 0.0f;
}

__device__ __forceinline__ float4 fma4(float s, float4 a, float4 b) {
    return make_float4(fmaf(s, a.x, b.x), fmaf(s, a.y, b.y),
                       fmaf(s, a.z, b.z), fmaf(s, a.w, b.w));
}

__device__ __forceinline__ float posenc(float cx, float cy, int o) {
    int r = o >> 4, f = o & 15;
    float base = (r < 2) ? cx : cy;
    float ang = 3.14f * base * (float)f / 200.0f;
    return ((r & 1) == 0) ? __sinf(ang) : __cosf(ang);
}

// Dual-token matmul on packed weights: out[o] += sum_c act[t][c]*w[c][o],
// o0=2*lane, o1=2*lane+1.
template <int PAIRS>
__device__ __forceinline__ void mm2p(const float* a0, const float* a1,
                                     const float4* __restrict__ P, int l,
                                     float2& r0, float2& r1)
{
    P += l;
    #pragma unroll 4
    for (int p = 0; p < PAIRS; p += 2) {
        float4 x0 = *(const float4*)(a0 + 2 * p);
        float4 x1 = *(const float4*)(a1 + 2 * p);
        float4 wA = P[p * 32];
        float4 wB = P[(p + 1) * 32];
        r0.x = fmaf(x0.x, wA.x, r0.x); r0.y = fmaf(x0.x, wA.y, r0.y);
        r0.x = fmaf(x0.y, wA.z, r0.x); r0.y = fmaf(x0.y, wA.w, r0.y);
        r1.x = fmaf(x1.x, wA.x, r1.x); r1.y = fmaf(x1.x, wA.y, r1.y);
        r1.x = fmaf(x1.y, wA.z, r1.x); r1.y = fmaf(x1.y, wA.w, r1.y);
        r0.x = fmaf(x0.z, wB.x, r0.x); r0.y = fmaf(x0.z, wB.y, r0.y);
        r0.x = fmaf(x0.w, wB.z, r0.x); r0.y = fmaf(x0.w, wB.w, r0.y);
        r1.x = fmaf(x1.z, wB.x, r1.x); r1.y = fmaf(x1.z, wB.y, r1.y);
        r1.x = fmaf(x1.w, wB.z, r1.x); r1.y = fmaf(x1.w, wB.w, r1.y);
    }
}

// Per-warp shared state for 2 tokens.
struct __align__(16) WarpSmem {
    float u[2][1056];     // 8 x 132 rows of u[h][c] (written in phase 8)
    float corr[2][88];    // 81 correlation values; [81..87] zeroed
    float attn[2][64];    // softmaxed attention
    float qlin[2][64];
    float A[2][64];       // gelu(fte1) -> attn_out -> ffn hidden
    float B[2][64];       // normed (+enc) vectors
    float sh[2][64];      // short (residual)
    float xs[2][64];      // final
};

// Reduce-scatter two independent v[8] arrays (partial scores for j=0..7)
// across lanes simultaneously (interleaved for SHFL-latency overlap).
// Each array ends with the full score for j=(l>>2)&7 in v*[0].
__device__ __forceinline__ void score_reduce2(float* a, float* b, int l) {
    bool up = (l & 16) != 0;
    #pragma unroll
    for (int i = 0; i < 4; ++i) {
        float sa = up ? a[i] : a[i + 4];
        float sb = up ? b[i] : b[i + 4];
        float ra = __shfl_xor_sync(0xffffffffu, sa, 16);
        float rb = __shfl_xor_sync(0xffffffffu, sb, 16);
        a[i] = (up ? a[i + 4] : a[i]) + ra;
        b[i] = (up ? b[i + 4] : b[i]) + rb;
    }
    up = (l & 8) != 0;
    #pragma unroll
    for (int i = 0; i < 2; ++i) {
        float sa = up ? a[i] : a[i + 2];
        float sb = up ? b[i] : b[i + 2];
        float ra = __shfl_xor_sync(0xffffffffu, sa, 8);
        float rb = __shfl_xor_sync(0xffffffffu, sb, 8);
        a[i] = (up ? a[i + 2] : a[i]) + ra;
        b[i] = (up ? b[i + 2] : b[i]) + rb;
    }
    up = (l & 4) != 0;
    {
        float sa = up ? a[0] : a[1];
        float sb = up ? b[0] : b[1];
        float ra = __shfl_xor_sync(0xffffffffu, sa, 4);
        float rb = __shfl_xor_sync(0xffffffffu, sb, 4);
        a[0] = (up ? a[1] : a[0]) + ra;
        b[0] = (up ? b[1] : b[0]) + rb;
    }
    a[0] += __shfl_xor_sync(0xffffffffu, a[0], 2);
    b[0] += __shfl_xor_sync(0xffffffffu, b[0], 2);
    a[0] += __shfl_xor_sync(0xffffffffu, a[0], 1);
    b[0] += __shfl_xor_sync(0xffffffffu, b[0], 1);
}

// Softmax over the 8-j group WITHOUT max subtraction (scores provably |s|<~5;
// __expf exact-safe; mathematically identical result).
__device__ __forceinline__ void softmax2(float s0, float s1, float& a0, float& a1) {
    float e0 = __expf(s0), e1 = __expf(s1);
    float t0 = e0, t1 = e1;
    t0 += __shfl_xor_sync(0xffffffffu, t0, 4);
    t1 += __shfl_xor_sync(0xffffffffu, t1, 4);
    t0 += __shfl_xor_sync(0xffffffffu, t0, 8);
    t1 += __shfl_xor_sync(0xffffffffu, t1, 8);
    t0 += __shfl_xor_sync(0xffffffffu, t0, 16);
    t1 += __shfl_xor_sync(0xffffffffu, t1, 16);
    a0 = __fdividef(e0, t0);
    a1 = __fdividef(e1, t1);
}

__global__ __launch_bounds__(64, 8) void decoder_kernel(
    const float* __restrict__ cost_maps,
    const float* __restrict__ cost_memory,
    const float* __restrict__ coords1,
    const float* __restrict__ fte_b1,
    const float* __restrict__ fte_b2,
    const float* __restrict__ ln1_g, const float* __restrict__ ln1_b,
    const float* __restrict__ ln2_g, const float* __restrict__ ln2_b,
    const float* __restrict__ bq,  const float* __restrict__ bv,
    const float* __restrict__ bp,
    const float* __restrict__ fb1, const float* __restrict__ fb2,
    float* __restrict__ out)
{
    __shared__ WarpSmem ts[2];
    const int warp = threadIdx.x >> 5;
    const int l = threadIdx.x & 31;
    const int n0 = blockIdx.x * 4 + warp * 2;   // tokens n0, n0+1
    WarpSmem& S = ts[warp];

    const int b = n0 >> 12;
    const int pix0 = n0 & 4095;
    const float cx0 = coords1[b * 8192 + pix0];
    const float cy0 = coords1[b * 8192 + 4096 + pix0];
    const float cx1 = coords1[b * 8192 + pix0 + 1];
    const float cy1 = coords1[b * 8192 + 4096 + pix0 + 1];
    const int o0 = 2 * l, o1 = 2 * l + 1;

    // ---- phase 1: bilinear correlation sampling (si fast across lanes) ----
    #pragma unroll
    for (int t = 0; t < 2; ++t) {
        const float* cmap = cost_maps + (size_t)(n0 + t) * 4096;
        const float cx = t ? cx1 : cx0;
        const float cy = t ? cy1 : cy0;
        for (int ss = l; ss < 81; ss += 32) {
            int si = ss % 9, sj = ss / 9;
            float px = cx + (float)(si - 4);
            float py = cy + (float)(sj - 4);
            float fx0 = floorf(px), fy0 = floorf(py);
            float wx = px - fx0, wy = py - fy0;
            int ix = (int)fx0, iy = (int)fy0;
            float v00 = samp_map(cmap, ix,     iy);
            float v10 = samp_map(cmap, ix + 1, iy);
            float v01 = samp_map(cmap, ix,     iy + 1);
            float v11 = samp_map(cmap, ix + 1, iy + 1);
            S.corr[t][si * 9 + sj] =
                  v00 * (1.f - wx) * (1.f - wy) + v10 * wx * (1.f - wy)
                + v01 * (1.f - wx) * wy         + v11 * wx * wy;
        }
        if (l < 7) S.corr[t][81 + l] = 0.f;   // zero pad rows 81..87
    }
    __syncwarp();

    // ---- phase 2: FTE1 = gelu(corr @ W1 + b1) ----
    {
        float2 bb = *(const float2*)(fte_b1 + o0);
        float2 r0 = bb, r1 = bb;
        mm2p<42>(S.corr[0], S.corr[1], g_wpk + OFF_W1, l, r0, r1);
        *(float2*)&S.A[0][o0] = make_float2(gelu_exact(r0.x), gelu_exact(r0.y));
        *(float2*)&S.A[1][o0] = make_float2(gelu_exact(r1.x), gelu_exact(r1.y));
    }
    __syncwarp();

    // ---- phase 3: query = A @ W2 + b2 (= short) ----
    float2 q0, q1;
    {
        float2 bb = *(const float2*)(fte_b2 + o0);
        q0 = bb; q1 = bb;
        mm2p<32>(S.A[0], S.A[1], g_wpk + OFF_W2, l, q0, q1);
        *(float2*)&S.sh[0][o0] = q0;
        *(float2*)&S.sh[1][o0] = q1;
    }

    // ---- phase 4: layernorm1 + positional encoding ----
    {
        float s0 = q0.x + q0.y, s1 = q1.x + q1.y;
        #pragma unroll
        for (int off = 16; off; off >>= 1) {
            s0 += __shfl_xor_sync(0xffffffffu, s0, off);
            s1 += __shfl_xor_sync(0xffffffffu, s1, off);
        }
        float m0 = s0 * (1.f / 64.f), m1 = s1 * (1.f / 64.f);
        float d00 = q0.x - m0, d01 = q0.y - m0;
        float d10 = q1.x - m1, d11 = q1.y - m1;
        float v0 = d00 * d00 + d01 * d01, v1 = d10 * d10 + d11 * d11;
        #pragma unroll
        for (int off = 16; off; off >>= 1) {
            v0 += __shfl_xor_sync(0xffffffffu, v0, off);
            v1 += __shfl_xor_sync(0xffffffffu, v1, off);
        }
        float i0 = rsqrtf(v0 * (1.f / 64.f) + 1e-5f);
        float i1 = rsqrtf(v1 * (1.f / 64.f) + 1e-5f);
        float2 g2 = *(const float2*)(ln1_g + o0);
        float2 b2v = *(const float2*)(ln1_b + o0);
        float e00 = posenc(cx0, cy0, o0), e01 = posenc(cx0, cy0, o1);
        float e10 = posenc(cx1, cy1, o0), e11 = posenc(cx1, cy1, o1);
        *(float2*)&S.B[0][o0] = make_float2(d00 * i0 * g2.x + b2v.x + e00,
                                            d01 * i0 * g2.y + b2v.y + e01);
        *(float2*)&S.B[1][o0] = make_float2(d10 * i1 * g2.x + b2v.x + e10,
                                            d11 * i1 * g2.y + b2v.y + e11);
    }
    __syncwarp();

    // ---- phase 5: qlin = B @ wq + bq ----
    {
        float2 bb = *(const float2*)(bq + o0);
        float2 r0 = bb, r1 = bb;
        mm2p<32>(S.B[0], S.B[1], g_wpk + OFF_WQ, l, r0, r1);
        *(float2*)&S.qlin[0][o0] = r0;
        *(float2*)&S.qlin[1][o0] = r1;
    }
    __syncwarp();

    // ---- phases 6-8 fused, DUAL-TOKEN (wk fragments shared across tokens) ----
    {
        float4 cmf0[8], cmf1[8];
        const float* cmb0 = cost_memory + (size_t)n0 * 1024 + 4 * l;
        const float* cmb1 = cmb0 + 1024;
        #pragma unroll
        for (int j = 0; j < 8; ++j) {
            cmf0[j] = *(const float4*)(cmb0 + j * 128);
            cmf1[j] = *(const float4*)(cmb1 + j * 128);
        }
        const float4* wk4 = (const float4*)g_wk_t;
        const float scale = 0.35355339059327373f;
        #pragma unroll
        for (int h = 0; h < 8; ++h) {
            float q0v[8], q1v[8];
            *(float4*)&q0v[0] = *(const float4*)&S.qlin[0][h * 8];
            *(float4*)&q0v[4] = *(const float4*)&S.qlin[0][h * 8 + 4];
            *(float4*)&q1v[0] = *(const float4*)&S.qlin[1][h * 8];
            *(float4*)&q1v[4] = *(const float4*)&S.qlin[1][h * 8 + 4];
            float4 tf0 = make_float4(0.f, 0.f, 0.f, 0.f), tf1 = tf0;
            #pragma unroll
            for (int e = 0; e < 8; ++e) {
                float4 w = wk4[(h * 8 + e) * 32 + l];
                tf0 = fma4(q0v[e], w, tf0);
                tf1 = fma4(q1v[e], w, tf1);
            }
            float v0[8], v1[8];
            #pragma unroll
            for (int j = 0; j < 8; ++j) {
                v0[j] = fmaf(tf0.x, cmf0[j].x, fmaf(tf0.y, cmf0[j].y,
                        fmaf(tf0.z, cmf0[j].z, tf0.w * cmf0[j].w)));
                v1[j] = fmaf(tf1.x, cmf1[j].x, fmaf(tf1.y, cmf1[j].y,
                        fmaf(tf1.z, cmf1[j].z, tf1.w * cmf1[j].w)));
            }
            score_reduce2(v0, v1, l);
            float a0, a1;
            softmax2(v0[0] * scale, v1[0] * scale, a0, a1);
            if ((l & 3) == 0) {
                S.attn[0][h * 8 + ((l >> 2) & 7)] = a0;
                S.attn[1][h * 8 + ((l >> 2) & 7)] = a1;
            }
        }
        __syncwarp();   // attn visible

        // u[h] = sum_j attn[h][j] * cm[j]  (per token, cm frags still live)
        {
            float4 ua[8];
            #pragma unroll
            for (int h = 0; h < 8; ++h) ua[h] = make_float4(0.f, 0.f, 0.f, 0.f);
            #pragma unroll
            for (int j = 0; j < 8; ++j) {
                float4 m = cmf0[j];
                #pragma unroll
                for (int h = 0; h < 8; ++h)
                    ua[h] = fma4(S.attn[0][h * 8 + j], m, ua[h]);
            }
            #pragma unroll
            for (int h = 0; h < 8; ++h)
                *(float4*)&S.u[0][h * 132 + 4 * l] = ua[h];
        }
        {
            float4 ua[8];
            #pragma unroll
            for (int h = 0; h < 8; ++h) ua[h] = make_float4(0.f, 0.f, 0.f, 0.f);
            #pragma unroll
            for (int j = 0; j < 8; ++j) {
                float4 m = cmf1[j];
                #pragma unroll
                for (int h = 0; h < 8; ++h)
                    ua[h] = fma4(S.attn[1][h * 8 + j], m, ua[h]);
            }
            #pragma unroll
            for (int h = 0; h < 8; ++h)
                *(float4*)&S.u[1][h * 132 + 4 * l] = ua[h];
        }
    }
    __syncwarp();

    // ---- phase 9: out = u @ wv + bv ----
    {
        float2 bb = *(const float2*)(bv + o0);
        float2 r0 = bb, r1 = bb;
        const int h = l >> 2;   // head of both o0 and o1
        mm2p<64>(&S.u[0][h * 132], &S.u[1][h * 132], g_wpk + OFF_WV, l, r0, r1);
        *(float2*)&S.A[0][o0] = r0;
        *(float2*)&S.A[1][o0] = r1;
    }
    __syncwarp();

    // ---- phase 10: x = concat(out, short) @ wp + bp + short ----
    float2 x0, x1;
    {
        float2 bb = *(const float2*)(bp + o0);
        x0 = bb; x1 = bb;
        mm2p<32>(S.A[0], S.A[1], g_wpk + OFF_WP1, l, x0, x1);
        mm2p<32>(S.sh[0], S.sh[1], g_wpk + OFF_WP2, l, x0, x1);
        float2 sh0 = *(const float2*)&S.sh[0][o0];
        float2 sh1 = *(const float2*)&S.sh[1][o0];
        x0.x += sh0.x; x0.y += sh0.y;
        x1.x += sh1.x; x1.y += sh1.y;
    }

    // ---- phase 11: layernorm2 ----
    {
        float s0 = x0.x + x0.y, s1 = x1.x + x1.y;
        #pragma unroll
        for (int off = 16; off; off >>= 1) {
            s0 += __shfl_xor_sync(0xffffffffu, s0, off);
            s1 += __shfl_xor_sync(0xffffffffu, s1, off);
        }
        float m0 = s0 * (1.f / 64.f), m1 = s1 * (1.f / 64.f);
        float d00 = x0.x - m0, d01 = x0.y - m0;
        float d10 = x1.x - m1, d11 = x1.y - m1;
        float v0 = d00 * d00 + d01 * d01, v1 = d10 * d10 + d11 * d11;
        #pragma unroll
        for (int off = 16; off; off >>= 1) {
            v0 += __shfl_xor_sync(0xffffffffu, v0, off);
            v1 += __shfl_xor_sync(0xffffffffu, v1, off);
        }
        float i0 = rsqrtf(v0 * (1.f / 64.f) + 1e-5f);
        float i1 = rsqrtf(v1 * (1.f / 64.f) + 1e-5f);
        float2 g2 = *(const float2*)(ln2_g + o0);
        float2 b2v = *(const float2*)(ln2_b + o0);
        *(float2*)&S.B[0][o0] = make_float2(d00 * i0 * g2.x + b2v.x,
                                            d01 * i0 * g2.y + b2v.y);
        *(float2*)&S.B[1][o0] = make_float2(d10 * i1 * g2.x + b2v.x,
                                            d11 * i1 * g2.y + b2v.y);
    }
    __syncwarp();

    // ---- phase 12: FFN hidden ----
    {
        float2 bb = *(const float2*)(fb1 + o0);
        float2 r0 = bb, r1 = bb;
        mm2p<32>(S.B[0], S.B[1], g_wpk + OFF_F1, l, r0, r1);
        *(float2*)&S.A[0][o0] = make_float2(gelu_exact(r0.x), gelu_exact(r0.y));
        *(float2*)&S.A[1][o0] = make_float2(gelu_exact(r1.x), gelu_exact(r1.y));
    }
    __syncwarp();

    // ---- phase 13: FFN out + residual ----
    {
        float2 bb = *(const float2*)(fb2 + o0);
        float2 r0 = bb, r1 = bb;
        mm2p<32>(S.A[0], S.A[1], g_wpk + OFF_F2, l, r0, r1);
        *(float2*)&S.xs[0][o0] = make_float2(x0.x + r0.x, x0.y + r0.y);
        *(float2*)&S.xs[1][o0] = make_float2(x1.x + r1.x, x1.y + r1.y);
    }

    // ---- phase 14: block-staged transposed writeout (STG.128) ----
    __syncthreads();
    {
        int nb = blockIdx.x * 4;
        int bb = nb >> 12;
        int px = nb & 4095;
        float* cg = out + FLOW_SZ + (size_t)bb * 64 * 4096 + px;
        int o = threadIdx.x;   // 0..63
        float4 v = make_float4(ts[0].xs[0][o], ts[0].xs[1][o],
                               ts[1].xs[0][o], ts[1].xs[1][o]);
        *(float4*)(cg + (size_t)o * 4096) = v;
    }
}

// ============================================================================
// Convex upsampling, 16 pixels per block. Blocks 0..37 pack the matmul
// weights into g_wpk; blocks 38..69 transpose wk into g_wk_t.
// ============================================================================
__global__ __launch_bounds__(256) void upsample_kernel(
    const float* __restrict__ coords1,
    const float* __restrict__ up_mask,
    const float* __restrict__ fte_w1,
    const float* __restrict__ fte_w2,
    const float* __restrict__ wq,
    const float* __restrict__ wk,
    const float* __restrict__ wv,
    const float* __restrict__ wp,
    const float* __restrict__ fw1,
    const float* __restrict__ fw2,
    float* __restrict__ out)
{
    extern __shared__ float dyn[];
    const int PAD = 20;            // slab row stride in floats (float4-aligned)
    float* slab = dyn;             // 576 * PAD
    float* fl   = dyn + 576 * PAD; // 2 * 3 * 18

    int blk = blockIdx.x;
    int tid = threadIdx.x;

    if (blk < 38) {
        int i = blk * 256 + tid;      // float4 index into g_wpk
        if (i < WPK_TOTAL) {
            int pr = i >> 5, l = i & 31;
            int oA = 2 * l, oB = 2 * l + 1;
            float4 v;
            if (pr < 42) {
                int c = 2 * pr;
                v.x = (c < 81)     ? fte_w1[oA * 81 + c]     : 0.f;
                v.y = (c < 81)     ? fte_w1[oB * 81 + c]     : 0.f;
                v.z = (c + 1 < 81) ? fte_w1[oA * 81 + c + 1] : 0.f;
                v.w = (c + 1 < 81) ? fte_w1[oB * 81 + c + 1] : 0.f;
            } else if (pr < 74) {
                int c = 2 * (pr - 42);
                v = make_float4(fte_w2[oA * 64 + c], fte_w2[oB * 64 + c],
                                fte_w2[oA * 64 + c + 1], fte_w2[oB * 64 + c + 1]);
            } else if (pr < 106) {
                int c = 2 * (pr - 74);
                v = make_float4(wq[c * 64 + oA], wq[c * 64 + oB],
                                wq[(c + 1) * 64 + oA], wq[(c + 1) * 64 + oB]);
            } else if (pr < 170) {
                int c = 2 * (pr - 106);
                v = make_float4(wv[c * 64 + oA], wv[c * 64 + oB],
                                wv[(c + 1) * 64 + oA], wv[(c + 1) * 64 + oB]);
            } else if (pr < 234) {
                int c = 2 * (pr - 170);   // rows 0..127 of wp (WP1 then WP2)
                v = make_float4(wp[c * 64 + oA], wp[c * 64 + oB],
                                wp[(c + 1) * 64 + oA], wp[(c + 1) * 64 + oB]);
            } else if (pr < 266) {
                int c = 2 * (pr - 234);
                v = make_float4(fw1[c * 64 + oA], fw1[c * 64 + oB],
                                fw1[(c + 1) * 64 + oA], fw1[(c + 1) * 64 + oB]);
            } else {
                int c = 2 * (pr - 266);
                v = make_float4(fw2[c * 64 + oA], fw2[c * 64 + oB],
                                fw2[(c + 1) * 64 + oA], fw2[(c + 1) * 64 + oB]);
            }
            g_wpk[i] = v;
        }
    } else if (blk < 70) {
        int i = (blk - 38) * 256 + tid;   // [0, 8192)
        int d = i >> 7, c = i & 127;
        g_wk_t[i] = wk[c * 64 + d];
    }

    // 512 blocks: b (2) x y (64) x x-tile (4 of 16 px)
    const int b  = blk >> 8;           // 0..1
    const int r2 = blk & 255;
    const int y  = r2 >> 2;            // 0..63
    const int x0 = (r2 & 3) << 4;      // 0,16,32,48

    // load mask slab: 576 channels x 16 px = 4 float4 per channel
    const float* mbase = up_mask + (size_t)b * 576 * 4096 + y * 64 + x0;
    for (int idx = tid; idx < 576 * 4; idx += 256) {
        int ch = idx >> 2, k = idx & 3;
        *(float4*)&slab[ch * PAD + 4 * k] =
            *(const float4*)(mbase + (size_t)ch * 4096 + 4 * k);
    }
    // flow neighborhood: rows y-1..y+1, cols x0-1..x0+16 (18 wide), 2 comps
    for (int idx = tid; idx < 2 * 3 * 18; idx += 256) {
        int c = idx / 54, rr = idx % 54, r = rr / 18, cc = rr % 18;
        int yy = y + r - 1, xx = x0 + cc - 1;
        float v = 0.0f;
        if ((unsigned)yy < 64u && (unsigned)xx < 64u) {
            float coord = coords1[b * 8192 + c * 4096 + yy * 64 + xx];
            v = 8.0f * (coord - (float)(c == 0 ? xx : yy));
        }
        fl[c * 54 + r * 18 + cc] = v;
    }
    __syncthreads();

    // 1024 sites: site = i*128 + p*8 + j  (i sub-row, p pixel, j sub-col)
    // Softmax without max subtraction: mask ~N(0,1), |w| small, __expf safe.
    float* ob0 = out + (size_t)b * 2 * 512 * 512 + (size_t)(8 * y) * 512 + x0 * 8;
    for (int it = 0; it < 4; ++it) {
        int site = it * 256 + tid;
        int i = site >> 7;
        int rr = site & 127;
        int p = rr >> 3, j = rr & 7;
        int ij = i * 8 + j;
        float w[9];
        float s = 0.f;
        #pragma unroll
        for (int kk = 0; kk < 9; ++kk) {
            w[kk] = __expf(slab[(kk * 64 + ij) * PAD + p]);
            s += w[kk];
        }
        float inv = __fdividef(1.0f, s);
        float u0 = 0.f, u1 = 0.f;
        #pragma unroll
        for (int kk = 0; kk < 9; ++kk) {
            int dy = kk / 3, dx = kk - dy * 3;
            u0 = fmaf(w[kk], fl[0 * 54 + dy * 18 + p + dx], u0);
            u1 = fmaf(w[kk], fl[1 * 54 + dy * 18 + p + dx], u1);
        }
        float* o = ob0 + (size_t)i * 512 + p * 8 + j;
        o[0] = u0 * inv;
        o[512 * 512] = u1 * inv;
    }
}

extern "C" void kernel_launch(void* const* d_in, const int* in_sizes, int n_in,
                              void* d_out, int out_size) {
    const float* cost_maps   = (const float*)d_in[0];
    const float* cost_memory = (const float*)d_in[1];
    const float* coords1     = (const float*)d_in[2];
    const float* up_mask     = (const float*)d_in[3];
    const float* fte_w1      = (const float*)d_in[4];
    const float* fte_b1      = (const float*)d_in[5];
    const float* fte_w2      = (const float*)d_in[6];
    const float* fte_b2      = (const float*)d_in[7];
    const float* ln1_g       = (const float*)d_in[8];
    const float* ln1_b       = (const float*)d_in[9];
    const float* ln2_g       = (const float*)d_in[10];
    const float* ln2_b       = (const float*)d_in[11];
    const float* wq          = (const float*)d_in[12];
    const float* bq          = (const float*)d_in[13];
    const float* wk          = (const float*)d_in[14];
    const float* wv          = (const float*)d_in[16];
    const float* bv          = (const float*)d_in[17];
    const float* wp          = (const float*)d_in[18];
    const float* bp          = (const float*)d_in[19];
    const float* fw1         = (const float*)d_in[20];
    const float* fb1         = (const float*)d_in[21];
    const float* fw2         = (const float*)d_in[22];
    const float* fb2         = (const float*)d_in[23];
    float* out = (float*)d_out;

    const int smem_bytes = (576 * 20 + 2 * 3 * 18) * 4;   // 46,512 B
    cudaFuncSetAttribute(upsample_kernel,
                         cudaFuncAttributeMaxDynamicSharedMemorySize, smem_bytes);

    upsample_kernel<<<512, 256, smem_bytes>>>(coords1, up_mask, fte_w1, fte_w2,
                                              wq, wk, wv, wp, fw1, fw2, out);
    decoder_kernel<<<2048, 64>>>(cost_maps, cost_memory, coords1,
                                 fte_b1, fte_b2,
                                 ln1_g, ln1_b, ln2_g, ln2_b,
                                 bq, bv, bp, fb1, fb2, out);
}

// round 16
// speedup vs baseline: 1.1555x; 1.0078x over previous
#include <cuda_runtime.h>
#include <math.h>

#define FLOW_SZ 1048576       // 2*2*512*512

// ---- packed weights, float2-per-output layout (filled by upsample prep) ----
// g_wpk2[region + p*64 + o] = float2(w[2p][o], w[2p+1][o])
// Regions (in pair-rows): W1 [0,42) (rows 81..83 zero-padded), W2 [42,74),
// WQ [74,106), WV [106,170), WP1 [170,202), WP2 [202,234), F1 [234,266), F2 [266,298)
#define OFF2_W1  0
#define OFF2_W2  (42 * 64)
#define OFF2_WQ  (74 * 64)
#define OFF2_WV  (106 * 64)
#define OFF2_WP1 (170 * 64)
#define OFF2_WP2 (202 * 64)
#define OFF2_F1  (234 * 64)
#define OFF2_F2  (266 * 64)
#define WPK2_TOTAL (298 * 64)   // 19072 float2

__device__ __align__(16) float2 g_wpk2[WPK2_TOTAL];
__device__ __align__(16) float g_wk_t[64 * 128];   // g_wk_t[d*128+c] = wk[c*64+d]

__device__ __forceinline__ float gelu_exact(float x) {
    return 0.5f * x * (1.0f + erff(x * 0.70710678118654752f));
}

__device__ __forceinline__ float samp_map(const float* __restrict__ p, int ix, int iy) {
    if ((unsigned)ix < 64u && (unsigned)iy < 64u) return p[iy * 64 + ix];
    return 0.0f;
}

__device__ __forceinline__ float4 fma4(float s, float4 a, float4 b) {
    return make_float4(fmaf(s, a.x, b.x), fmaf(s, a.y, b.y),
                       fmaf(s, a.z, b.z), fmaf(s, a.w, b.w));
}

__device__ __forceinline__ float posenc(float cx, float cy, int o) {
    int r = o >> 4, f = o & 15;
    float base = (r < 2) ? cx : cy;
    float ang = 3.14f * base * (float)f / 200.0f;
    return ((r & 1) == 0) ? __sinf(ang) : __cosf(ang);
}

// Quad-token, split-output matmul: lane owns ONE output o; accumulates
// r[t] += sum_c act[t][c] * w[c][o]. Weights: 1 LDG.64 per pair-row (warp
// reads 256B coalesced). PAIRS even.
template <int PAIRS>
__device__ __forceinline__ void mm4s(const float* a0, const float* a1,
                                     const float* a2, const float* a3,
                                     const float2* __restrict__ P, int o,
                                     float& r0, float& r1, float& r2, float& r3)
{
    P += o;
    #pragma unroll 4
    for (int p = 0; p < PAIRS; p += 2) {
        float4 x0 = *(const float4*)(a0 + 2 * p);
        float4 x1 = *(const float4*)(a1 + 2 * p);
        float4 x2 = *(const float4*)(a2 + 2 * p);
        float4 x3 = *(const float4*)(a3 + 2 * p);
        float2 wA = P[p * 64];
        float2 wB = P[(p + 1) * 64];
        r0 = fmaf(x0.x, wA.x, r0); r0 = fmaf(x0.y, wA.y, r0);
        r1 = fmaf(x1.x, wA.x, r1); r1 = fmaf(x1.y, wA.y, r1);
        r2 = fmaf(x2.x, wA.x, r2); r2 = fmaf(x2.y, wA.y, r2);
        r3 = fmaf(x3.x, wA.x, r3); r3 = fmaf(x3.y, wA.y, r3);
        r0 = fmaf(x0.z, wB.x, r0); r0 = fmaf(x0.w, wB.y, r0);
        r1 = fmaf(x1.z, wB.x, r1); r1 = fmaf(x1.w, wB.y, r1);
        r2 = fmaf(x2.z, wB.x, r2); r2 = fmaf(x2.w, wB.y, r2);
        r3 = fmaf(x3.z, wB.x, r3); r3 = fmaf(x3.w, wB.y, r3);
    }
}

// Per-block shared state for 4 tokens.
struct __align__(16) BlkSmem {
    float u[4][1056];     // 8 x 132 rows of u[h][c] per token
    float corr[4][88];    // 81 correlation values; [81..87] zeroed
    float attn[4][64];
    float qlin[4][64];
    float A[4][64];       // gelu(fte1) -> attn_out -> ffn hidden
    float B[4][64];       // normed (+enc) vectors
    float sh[4][64];      // short (residual)
    float xs[4][64];      // final
    float part[2][4][2];  // LN partials: [warp][token][{sum, sumsq}]
};

// Reduce-scatter two independent v[8] arrays across lanes (interleaved).
__device__ __forceinline__ void score_reduce2(float* a, float* b, int l) {
    bool up = (l & 16) != 0;
    #pragma unroll
    for (int i = 0; i < 4; ++i) {
        float sa = up ? a[i] : a[i + 4];
        float sb = up ? b[i] : b[i + 4];
        float ra = __shfl_xor_sync(0xffffffffu, sa, 16);
        float rb = __shfl_xor_sync(0xffffffffu, sb, 16);
        a[i] = (up ? a[i + 4] : a[i]) + ra;
        b[i] = (up ? b[i + 4] : b[i]) + rb;
    }
    up = (l & 8) != 0;
    #pragma unroll
    for (int i = 0; i < 2; ++i) {
        float sa = up ? a[i] : a[i + 2];
        float sb = up ? b[i] : b[i + 2];
        float ra = __shfl_xor_sync(0xffffffffu, sa, 8);
        float rb = __shfl_xor_sync(0xffffffffu, sb, 8);
        a[i] = (up ? a[i + 2] : a[i]) + ra;
        b[i] = (up ? b[i + 2] : b[i]) + rb;
    }
    up = (l & 4) != 0;
    {
        float sa = up ? a[0] : a[1];
        float sb = up ? b[0] : b[1];
        float ra = __shfl_xor_sync(0xffffffffu, sa, 4);
        float rb = __shfl_xor_sync(0xffffffffu, sb, 4);
        a[0] = (up ? a[1] : a[0]) + ra;
        b[0] = (up ? b[1] : b[0]) + rb;
    }
    a[0] += __shfl_xor_sync(0xffffffffu, a[0], 2);
    b[0] += __shfl_xor_sync(0xffffffffu, b[0], 2);
    a[0] += __shfl_xor_sync(0xffffffffu, a[0], 1);
    b[0] += __shfl_xor_sync(0xffffffffu, b[0], 1);
}

// Softmax over 8-j group without max subtraction (scores tiny; exact-safe).
__device__ __forceinline__ void softmax2(float s0, float s1, float& a0, float& a1) {
    float e0 = __expf(s0), e1 = __expf(s1);
    float t0 = e0, t1 = e1;
    t0 += __shfl_xor_sync(0xffffffffu, t0, 4);
    t1 += __shfl_xor_sync(0xffffffffu, t1, 4);
    t0 += __shfl_xor_sync(0xffffffffu, t0, 8);
    t1 += __shfl_xor_sync(0xffffffffu, t1, 8);
    t0 += __shfl_xor_sync(0xffffffffu, t0, 16);
    t1 += __shfl_xor_sync(0xffffffffu, t1, 16);
    a0 = __fdividef(e0, t0);
    a1 = __fdividef(e1, t1);
}

__global__ __launch_bounds__(64, 8) void decoder_kernel(
    const float* __restrict__ cost_maps,
    const float* __restrict__ cost_memory,
    const float* __restrict__ coords1,
    const float* __restrict__ fte_b1,
    const float* __restrict__ fte_b2,
    const float* __restrict__ ln1_g, const float* __restrict__ ln1_b,
    const float* __restrict__ ln2_g, const float* __restrict__ ln2_b,
    const float* __restrict__ bq,  const float* __restrict__ bv,
    const float* __restrict__ bp,
    const float* __restrict__ fb1, const float* __restrict__ fb2,
    float* __restrict__ out)
{
    __shared__ BlkSmem S;
    const int tid  = threadIdx.x;
    const int warp = tid >> 5;
    const int l    = tid & 31;
    const int o    = tid;               // this lane's output dim (0..63)
    const int n0   = blockIdx.x * 4;    // tokens n0..n0+3 (never cross batch)
    const int b    = n0 >> 12;
    const int pix0 = n0 & 4095;

    float cx[4], cy[4];
    #pragma unroll
    for (int t = 0; t < 4; ++t) {
        cx[t] = coords1[b * 8192 + pix0 + t];
        cy[t] = coords1[b * 8192 + 4096 + pix0 + t];
    }

    // ---- phase 1: bilinear sampling; warp w handles tokens 2w, 2w+1 ----
    #pragma unroll
    for (int tt = 0; tt < 2; ++tt) {
        const int t = 2 * warp + tt;
        const float* cmap = cost_maps + (size_t)(n0 + t) * 4096;
        for (int ss = l; ss < 81; ss += 32) {
            int si = ss % 9, sj = ss / 9;
            float px = cx[t] + (float)(si - 4);
            float py = cy[t] + (float)(sj - 4);
            float fx0 = floorf(px), fy0 = floorf(py);
            float wx = px - fx0, wy = py - fy0;
            int ix = (int)fx0, iy = (int)fy0;
            float v00 = samp_map(cmap, ix,     iy);
            float v10 = samp_map(cmap, ix + 1, iy);
            float v01 = samp_map(cmap, ix,     iy + 1);
            float v11 = samp_map(cmap, ix + 1, iy + 1);
            S.corr[t][si * 9 + sj] =
                  v00 * (1.f - wx) * (1.f - wy) + v10 * wx * (1.f - wy)
                + v01 * (1.f - wx) * wy         + v11 * wx * wy;
        }
        if (l < 7) S.corr[t][81 + l] = 0.f;
    }
    __syncthreads();

    // ---- phase 2: FTE1 = gelu(corr @ W1 + b1) ----
    {
        float bb = fte_b1[o];
        float r0 = bb, r1 = bb, r2 = bb, r3 = bb;
        mm4s<42>(S.corr[0], S.corr[1], S.corr[2], S.corr[3],
                 g_wpk2 + OFF2_W1, o, r0, r1, r2, r3);
        S.A[0][o] = gelu_exact(r0);
        S.A[1][o] = gelu_exact(r1);
        S.A[2][o] = gelu_exact(r2);
        S.A[3][o] = gelu_exact(r3);
    }
    __syncthreads();

    // ---- phase 3: query = A @ W2 + b2 (= short) ----
    float q[4];
    {
        float bb = fte_b2[o];
        q[0] = bb; q[1] = bb; q[2] = bb; q[3] = bb;
        mm4s<32>(S.A[0], S.A[1], S.A[2], S.A[3],
                 g_wpk2 + OFF2_W2, o, q[0], q[1], q[2], q[3]);
        #pragma unroll
        for (int t = 0; t < 4; ++t) S.sh[t][o] = q[t];
    }

    // ---- phase 4: layernorm1 (cross-warp partials) + positional encoding ----
    {
        float s[4], sq[4];
        #pragma unroll
        for (int t = 0; t < 4; ++t) { s[t] = q[t]; sq[t] = q[t] * q[t]; }
        #pragma unroll
        for (int off = 16; off; off >>= 1) {
            #pragma unroll
            for (int t = 0; t < 4; ++t) {
                s[t]  += __shfl_xor_sync(0xffffffffu, s[t],  off);
                sq[t] += __shfl_xor_sync(0xffffffffu, sq[t], off);
            }
        }
        if (l == 0) {
            #pragma unroll
            for (int t = 0; t < 4; ++t) {
                S.part[warp][t][0] = s[t];
                S.part[warp][t][1] = sq[t];
            }
        }
        __syncthreads();
        float g = ln1_g[o], be = ln1_b[o];
        #pragma unroll
        for (int t = 0; t < 4; ++t) {
            float sum = S.part[0][t][0] + S.part[1][t][0];
            float sqs = S.part[0][t][1] + S.part[1][t][1];
            float mean = sum * (1.f / 64.f);
            float var  = sqs * (1.f / 64.f) - mean * mean;
            float inv  = rsqrtf(var + 1e-5f);
            S.B[t][o] = (q[t] - mean) * inv * g + be + posenc(cx[t], cy[t], o);
        }
    }
    __syncthreads();

    // ---- phase 5: qlin = B @ wq + bq ----
    {
        float bb = bq[o];
        float r0 = bb, r1 = bb, r2 = bb, r3 = bb;
        mm4s<32>(S.B[0], S.B[1], S.B[2], S.B[3],
                 g_wpk2 + OFF2_WQ, o, r0, r1, r2, r3);
        S.qlin[0][o] = r0; S.qlin[1][o] = r1;
        S.qlin[2][o] = r2; S.qlin[3][o] = r3;
    }
    __syncthreads();

    // ---- phases 6-8: attention; warp w handles tokens 2w, 2w+1 (R15 path) ----
    {
        const int t0 = 2 * warp;
        float4 cmf0[8], cmf1[8];
        const float* cmb0 = cost_memory + (size_t)(n0 + t0) * 1024 + 4 * l;
        const float* cmb1 = cmb0 + 1024;
        #pragma unroll
        for (int j = 0; j < 8; ++j) {
            cmf0[j] = *(const float4*)(cmb0 + j * 128);
            cmf1[j] = *(const float4*)(cmb1 + j * 128);
        }
        const float4* wk4 = (const float4*)g_wk_t;
        const float scale = 0.35355339059327373f;
        #pragma unroll
        for (int h = 0; h < 8; ++h) {
            float q0v[8], q1v[8];
            *(float4*)&q0v[0] = *(const float4*)&S.qlin[t0][h * 8];
            *(float4*)&q0v[4] = *(const float4*)&S.qlin[t0][h * 8 + 4];
            *(float4*)&q1v[0] = *(const float4*)&S.qlin[t0 + 1][h * 8];
            *(float4*)&q1v[4] = *(const float4*)&S.qlin[t0 + 1][h * 8 + 4];
            float4 tf0 = make_float4(0.f, 0.f, 0.f, 0.f), tf1 = tf0;
            #pragma unroll
            for (int e = 0; e < 8; ++e) {
                float4 w = wk4[(h * 8 + e) * 32 + l];
                tf0 = fma4(q0v[e], w, tf0);
                tf1 = fma4(q1v[e], w, tf1);
            }
            float v0[8], v1[8];
            #pragma unroll
            for (int j = 0; j < 8; ++j) {
                v0[j] = fmaf(tf0.x, cmf0[j].x, fmaf(tf0.y, cmf0[j].y,
                        fmaf(tf0.z, cmf0[j].z, tf0.w * cmf0[j].w)));
                v1[j] = fmaf(tf1.x, cmf1[j].x, fmaf(tf1.y, cmf1[j].y,
                        fmaf(tf1.z, cmf1[j].z, tf1.w * cmf1[j].w)));
            }
            score_reduce2(v0, v1, l);
            float a0, a1;
            softmax2(v0[0] * scale, v1[0] * scale, a0, a1);
            if ((l & 3) == 0) {
                S.attn[t0][h * 8 + ((l >> 2) & 7)] = a0;
                S.attn[t0 + 1][h * 8 + ((l >> 2) & 7)] = a1;
            }
        }
        __syncwarp();

        {
            float4 ua[8];
            #pragma unroll
            for (int h = 0; h < 8; ++h) ua[h] = make_float4(0.f, 0.f, 0.f, 0.f);
            #pragma unroll
            for (int j = 0; j < 8; ++j) {
                float4 m = cmf0[j];
                #pragma unroll
                for (int h = 0; h < 8; ++h)
                    ua[h] = fma4(S.attn[t0][h * 8 + j], m, ua[h]);
            }
            #pragma unroll
            for (int h = 0; h < 8; ++h)
                *(float4*)&S.u[t0][h * 132 + 4 * l] = ua[h];
        }
        {
            float4 ua[8];
            #pragma unroll
            for (int h = 0; h < 8; ++h) ua[h] = make_float4(0.f, 0.f, 0.f, 0.f);
            #pragma unroll
            for (int j = 0; j < 8; ++j) {
                float4 m = cmf1[j];
                #pragma unroll
                for (int h = 0; h < 8; ++h)
                    ua[h] = fma4(S.attn[t0 + 1][h * 8 + j], m, ua[h]);
            }
            #pragma unroll
            for (int h = 0; h < 8; ++h)
                *(float4*)&S.u[t0 + 1][h * 132 + 4 * l] = ua[h];
        }
    }
    __syncthreads();

    // ---- phase 9: out = u @ wv + bv  (per-lane head row of u) ----
    {
        float bb = bv[o];
        float r0 = bb, r1 = bb, r2 = bb, r3 = bb;
        const int h = o >> 3;
        mm4s<64>(&S.u[0][h * 132], &S.u[1][h * 132],
                 &S.u[2][h * 132], &S.u[3][h * 132],
                 g_wpk2 + OFF2_WV, o, r0, r1, r2, r3);
        S.A[0][o] = r0; S.A[1][o] = r1; S.A[2][o] = r2; S.A[3][o] = r3;
    }
    __syncthreads();

    // ---- phase 10: x = concat(out, short) @ wp + bp + short ----
    float x[4];
    {
        float bb = bp[o];
        x[0] = bb; x[1] = bb; x[2] = bb; x[3] = bb;
        mm4s<32>(S.A[0], S.A[1], S.A[2], S.A[3],
                 g_wpk2 + OFF2_WP1, o, x[0], x[1], x[2], x[3]);
        mm4s<32>(S.sh[0], S.sh[1], S.sh[2], S.sh[3],
                 g_wpk2 + OFF2_WP2, o, x[0], x[1], x[2], x[3]);
        #pragma unroll
        for (int t = 0; t < 4; ++t) x[t] += S.sh[t][o];
    }

    // ---- phase 11: layernorm2 (cross-warp partials) ----
    {
        float s[4], sq[4];
        #pragma unroll
        for (int t = 0; t < 4; ++t) { s[t] = x[t]; sq[t] = x[t] * x[t]; }
        #pragma unroll
        for (int off = 16; off; off >>= 1) {
            #pragma unroll
            for (int t = 0; t < 4; ++t) {
                s[t]  += __shfl_xor_sync(0xffffffffu, s[t],  off);
                sq[t] += __shfl_xor_sync(0xffffffffu, sq[t], off);
            }
        }
        if (l == 0) {
            #pragma unroll
            for (int t = 0; t < 4; ++t) {
                S.part[warp][t][0] = s[t];
                S.part[warp][t][1] = sq[t];
            }
        }
        __syncthreads();
        float g = ln2_g[o], be = ln2_b[o];
        #pragma unroll
        for (int t = 0; t < 4; ++t) {
            float sum = S.part[0][t][0] + S.part[1][t][0];
            float sqs = S.part[0][t][1] + S.part[1][t][1];
            float mean = sum * (1.f / 64.f);
            float var  = sqs * (1.f / 64.f) - mean * mean;
            float inv  = rsqrtf(var + 1e-5f);
            S.B[t][o] = (x[t] - mean) * inv * g + be;
        }
    }
    __syncthreads();

    // ---- phase 12: FFN hidden ----
    {
        float bb = fb1[o];
        float r0 = bb, r1 = bb, r2 = bb, r3 = bb;
        mm4s<32>(S.B[0], S.B[1], S.B[2], S.B[3],
                 g_wpk2 + OFF2_F1, o, r0, r1, r2, r3);
        S.A[0][o] = gelu_exact(r0);
        S.A[1][o] = gelu_exact(r1);
        S.A[2][o] = gelu_exact(r2);
        S.A[3][o] = gelu_exact(r3);
    }
    __syncthreads();

    // ---- phase 13: FFN out + residual ----
    {
        float bb = fb2[o];
        float r0 = bb, r1 = bb, r2 = bb, r3 = bb;
        mm4s<32>(S.A[0], S.A[1], S.A[2], S.A[3],
                 g_wpk2 + OFF2_F2, o, r0, r1, r2, r3);
        S.xs[0][o] = x[0] + r0;
        S.xs[1][o] = x[1] + r1;
        S.xs[2][o] = x[2] + r2;
        S.xs[3][o] = x[3] + r3;
    }
    __syncthreads();

    // ---- phase 14: transposed writeout, STG.128 of 4 token values per row ----
    {
        float* cg = out + FLOW_SZ + (size_t)b * 64 * 4096 + pix0;
        float4 v = make_float4(S.xs[0][o], S.xs[1][o], S.xs[2][o], S.xs[3][o]);
        *(float4*)(cg + (size_t)o * 4096) = v;
    }
}

// ============================================================================
// Convex upsampling, 16 pixels per block. Blocks 0..74 pack g_wpk2 (float2
// per-output layout); blocks 75..106 transpose wk into g_wk_t.
// ============================================================================
__global__ __launch_bounds__(256) void upsample_kernel(
    const float* __restrict__ coords1,
    const float* __restrict__ up_mask,
    const float* __restrict__ fte_w1,
    const float* __restrict__ fte_w2,
    const float* __restrict__ wq,
    const float* __restrict__ wk,
    const float* __restrict__ wv,
    const float* __restrict__ wp,
    const float* __restrict__ fw1,
    const float* __restrict__ fw2,
    float* __restrict__ out)
{
    extern __shared__ float dyn[];
    const int PAD = 20;
    float* slab = dyn;             // 576 * PAD
    float* fl   = dyn + 576 * PAD; // 2 * 3 * 18

    int blk = blockIdx.x;
    int tid = threadIdx.x;

    if (blk < 75) {
        int i = blk * 256 + tid;
        if (i < WPK2_TOTAL) {
            int pr = i >> 6, o = i & 63;
            float2 v;
            if (pr < 42) {
                int c = 2 * pr;
                v.x = (c < 81)     ? fte_w1[o * 81 + c]     : 0.f;
                v.y = (c + 1 < 81) ? fte_w1[o * 81 + c + 1] : 0.f;
            } else if (pr < 74) {
                int c = 2 * (pr - 42);
                v = make_float2(fte_w2[o * 64 + c], fte_w2[o * 64 + c + 1]);
            } else if (pr < 106) {
                int c = 2 * (pr - 74);
                v = make_float2(wq[c * 64 + o], wq[(c + 1) * 64 + o]);
            } else if (pr < 170) {
                int c = 2 * (pr - 106);
                v = make_float2(wv[c * 64 + o], wv[(c + 1) * 64 + o]);
            } else if (pr < 234) {
                int c = 2 * (pr - 170);   // rows 0..127 of wp
                v = make_float2(wp[c * 64 + o], wp[(c + 1) * 64 + o]);
            } else if (pr < 266) {
                int c = 2 * (pr - 234);
                v = make_float2(fw1[c * 64 + o], fw1[(c + 1) * 64 + o]);
            } else {
                int c = 2 * (pr - 266);
                v = make_float2(fw2[c * 64 + o], fw2[(c + 1) * 64 + o]);
            }
            g_wpk2[i] = v;
        }
    } else if (blk < 107) {
        int i = (blk - 75) * 256 + tid;   // [0, 8192)
        int d = i >> 7, c = i & 127;
        g_wk_t[i] = wk[c * 64 + d];
    }

    // 512 blocks: b (2) x y (64) x x-tile (4 of 16 px)
    const int b  = blk >> 8;
    const int r2 = blk & 255;
    const int y  = r2 >> 2;
    const int x0 = (r2 & 3) << 4;

    const float* mbase = up_mask + (size_t)b * 576 * 4096 + y * 64 + x0;
    for (int idx = tid; idx < 576 * 4; idx += 256) {
        int ch = idx >> 2, k = idx & 3;
        *(float4*)&slab[ch * PAD + 4 * k] =
            *(const float4*)(mbase + (size_t)ch * 4096 + 4 * k);
    }
    for (int idx = tid; idx < 2 * 3 * 18; idx += 256) {
        int c = idx / 54, rr = idx % 54, r = rr / 18, cc = rr % 18;
        int yy = y + r - 1, xx = x0 + cc - 1;
        float v = 0.0f;
        if ((unsigned)yy < 64u && (unsigned)xx < 64u) {
            float coord = coords1[b * 8192 + c * 4096 + yy * 64 + xx];
            v = 8.0f * (coord - (float)(c == 0 ? xx : yy));
        }
        fl[c * 54 + r * 18 + cc] = v;
    }
    __syncthreads();

    float* ob0 = out + (size_t)b * 2 * 512 * 512 + (size_t)(8 * y) * 512 + x0 * 8;
    for (int it = 0; it < 4; ++it) {
        int site = it * 256 + tid;
        int i = site >> 7;
        int rr = site & 127;
        int p = rr >> 3, j = rr & 7;
        int ij = i * 8 + j;
        float w[9];
        float s = 0.f;
        #pragma unroll
        for (int kk = 0; kk < 9; ++kk) {
            w[kk] = __expf(slab[(kk * 64 + ij) * PAD + p]);
            s += w[kk];
        }
        float inv = __fdividef(1.0f, s);
        float u0 = 0.f, u1 = 0.f;
        #pragma unroll
        for (int kk = 0; kk < 9; ++kk) {
            int dy = kk / 3, dx = kk - dy * 3;
            u0 = fmaf(w[kk], fl[0 * 54 + dy * 18 + p + dx], u0);
            u1 = fmaf(w[kk], fl[1 * 54 + dy * 18 + p + dx], u1);
        }
        float* oo = ob0 + (size_t)i * 512 + p * 8 + j;
        oo[0] = u0 * inv;
        oo[512 * 512] = u1 * inv;
    }
}

extern "C" void kernel_launch(void* const* d_in, const int* in_sizes, int n_in,
                              void* d_out, int out_size) {
    const float* cost_maps   = (const float*)d_in[0];
    const float* cost_memory = (const float*)d_in[1];
    const float* coords1     = (const float*)d_in[2];
    const float* up_mask     = (const float*)d_in[3];
    const float* fte_w1      = (const float*)d_in[4];
    const float* fte_b1      = (const float*)d_in[5];
    const float* fte_w2      = (const float*)d_in[6];
    const float* fte_b2      = (const float*)d_in[7];
    const float* ln1_g       = (const float*)d_in[8];
    const float* ln1_b       = (const float*)d_in[9];
    const float* ln2_g       = (const float*)d_in[10];
    const float* ln2_b       = (const float*)d_in[11];
    const float* wq          = (const float*)d_in[12];
    const float* bq          = (const float*)d_in[13];
    const float* wk          = (const float*)d_in[14];
    const float* wv          = (const float*)d_in[16];
    const float* bv          = (const float*)d_in[17];
    const float* wp          = (const float*)d_in[18];
    const float* bp          = (const float*)d_in[19];
    const float* fw1         = (const float*)d_in[20];
    const float* fb1         = (const float*)d_in[21];
    const float* fw2         = (const float*)d_in[22];
    const float* fb2         = (const float*)d_in[23];
    float* out = (float*)d_out;

    const int smem_bytes = (576 * 20 + 2 * 3 * 18) * 4;   // 46,512 B
    cudaFuncSetAttribute(upsample_kernel,
                         cudaFuncAttributeMaxDynamicSharedMemorySize, smem_bytes);

    upsample_kernel<<<512, 256, smem_bytes>>>(coords1, up_mask, fte_w1, fte_w2,
                                              wq, wk, wv, wp, fw1, fw2, out);
    decoder_kernel<<<2048, 64>>>(cost_maps, cost_memory, coords1,
                                 fte_b1, fte_b2,
                                 ln1_g, ln1_b, ln2_g, ln2_b,
                                 bq, bv, bp, fb1, fb2, out);
}

// round 17
// speedup vs baseline: 1.1778x; 1.0193x over previous
#include <cuda_runtime.h>
#include <math.h>

#define FLOW_SZ 1048576       // 2*2*512*512

// ---- packed weights, float2-per-output layout (filled by upsample prep) ----
// g_wpk2[region + p*64 + o] = float2(w[2p][o], w[2p+1][o])
#define OFF2_W1  0
#define OFF2_W2  (42 * 64)
#define OFF2_WQ  (74 * 64)
#define OFF2_WV  (106 * 64)
#define OFF2_WP1 (170 * 64)
#define OFF2_WP2 (202 * 64)
#define OFF2_F1  (234 * 64)
#define OFF2_F2  (266 * 64)
#define WPK2_TOTAL (298 * 64)   // 19072 float2

__device__ __align__(16) float2 g_wpk2[WPK2_TOTAL];
__device__ __align__(16) float g_wk_t[64 * 128];   // g_wk_t[d*128+c] = wk[c*64+d]

__device__ __forceinline__ float gelu_exact(float x) {
    return 0.5f * x * (1.0f + erff(x * 0.70710678118654752f));
}

__device__ __forceinline__ float samp_map(const float* __restrict__ p, int ix, int iy) {
    if ((unsigned)ix < 64u && (unsigned)iy < 64u) return p[iy * 64 + ix];
    return 0.0f;
}

__device__ __forceinline__ float4 fma4(float s, float4 a, float4 b) {
    return make_float4(fmaf(s, a.x, b.x), fmaf(s, a.y, b.y),
                       fmaf(s, a.z, b.z), fmaf(s, a.w, b.w));
}
__device__ __forceinline__ float dot4(float4 a, float4 b) {
    return fmaf(a.x, b.x, fmaf(a.y, b.y, fmaf(a.z, b.z, a.w * b.w)));
}

__device__ __forceinline__ float posenc(float cx, float cy, int o) {
    int r = o >> 4, f = o & 15;
    float base = (r < 2) ? cx : cy;
    float ang = 3.14f * base * (float)f / 200.0f;
    return ((r & 1) == 0) ? __sinf(ang) : __cosf(ang);
}

// Quad-token, split-output matmul: lane owns ONE output o.
template <int PAIRS>
__device__ __forceinline__ void mm4s(const float* a0, const float* a1,
                                     const float* a2, const float* a3,
                                     const float2* __restrict__ P, int o,
                                     float& r0, float& r1, float& r2, float& r3)
{
    P += o;
    #pragma unroll 4
    for (int p = 0; p < PAIRS; p += 2) {
        float4 x0 = *(const float4*)(a0 + 2 * p);
        float4 x1 = *(const float4*)(a1 + 2 * p);
        float4 x2 = *(const float4*)(a2 + 2 * p);
        float4 x3 = *(const float4*)(a3 + 2 * p);
        float2 wA = P[p * 64];
        float2 wB = P[(p + 1) * 64];
        r0 = fmaf(x0.x, wA.x, r0); r0 = fmaf(x0.y, wA.y, r0);
        r1 = fmaf(x1.x, wA.x, r1); r1 = fmaf(x1.y, wA.y, r1);
        r2 = fmaf(x2.x, wA.x, r2); r2 = fmaf(x2.y, wA.y, r2);
        r3 = fmaf(x3.x, wA.x, r3); r3 = fmaf(x3.y, wA.y, r3);
        r0 = fmaf(x0.z, wB.x, r0); r0 = fmaf(x0.w, wB.y, r0);
        r1 = fmaf(x1.z, wB.x, r1); r1 = fmaf(x1.w, wB.y, r1);
        r2 = fmaf(x2.z, wB.x, r2); r2 = fmaf(x2.w, wB.y, r2);
        r3 = fmaf(x3.z, wB.x, r3); r3 = fmaf(x3.w, wB.y, r3);
    }
}

// Per-block shared state for 4 tokens. u rows hold cost_memory first
// (phases 0-7), then are overwritten in place by u[h][c] (phase 8).
struct __align__(16) BlkSmem {
    float u[4][1056];     // 8 x 132 rows
    float corr[4][88];
    float attn[4][64];
    float qlin[4][64];
    float A[4][64];
    float B[4][64];
    float sh[4][64];
    float xs[4][64];
    float part[2][4][2];  // LN partials [warp][token][{sum,sumsq}]
};

// Reduce-scatter FOUR independent v[8] arrays across lanes (interleaved
// shuffle chains). Each ends with the full sum for j=(l>>2)&7 in v*[0].
__device__ __forceinline__ void score_reduce4(float* a, float* b,
                                              float* c, float* d, int l) {
    bool up = (l & 16) != 0;
    #pragma unroll
    for (int i = 0; i < 4; ++i) {
        float sa = up ? a[i] : a[i + 4];
        float sb = up ? b[i] : b[i + 4];
        float sc = up ? c[i] : c[i + 4];
        float sd = up ? d[i] : d[i + 4];
        float ra = __shfl_xor_sync(0xffffffffu, sa, 16);
        float rb = __shfl_xor_sync(0xffffffffu, sb, 16);
        float rc = __shfl_xor_sync(0xffffffffu, sc, 16);
        float rd = __shfl_xor_sync(0xffffffffu, sd, 16);
        a[i] = (up ? a[i + 4] : a[i]) + ra;
        b[i] = (up ? b[i + 4] : b[i]) + rb;
        c[i] = (up ? c[i + 4] : c[i]) + rc;
        d[i] = (up ? d[i + 4] : d[i]) + rd;
    }
    up = (l & 8) != 0;
    #pragma unroll
    for (int i = 0; i < 2; ++i) {
        float sa = up ? a[i] : a[i + 2];
        float sb = up ? b[i] : b[i + 2];
        float sc = up ? c[i] : c[i + 2];
        float sd = up ? d[i] : d[i + 2];
        float ra = __shfl_xor_sync(0xffffffffu, sa, 8);
        float rb = __shfl_xor_sync(0xffffffffu, sb, 8);
        float rc = __shfl_xor_sync(0xffffffffu, sc, 8);
        float rd = __shfl_xor_sync(0xffffffffu, sd, 8);
        a[i] = (up ? a[i + 2] : a[i]) + ra;
        b[i] = (up ? b[i + 2] : b[i]) + rb;
        c[i] = (up ? c[i + 2] : c[i]) + rc;
        d[i] = (up ? d[i + 2] : d[i]) + rd;
    }
    up = (l & 4) != 0;
    {
        float sa = up ? a[0] : a[1];
        float sb = up ? b[0] : b[1];
        float sc = up ? c[0] : c[1];
        float sd = up ? d[0] : d[1];
        float ra = __shfl_xor_sync(0xffffffffu, sa, 4);
        float rb = __shfl_xor_sync(0xffffffffu, sb, 4);
        float rc = __shfl_xor_sync(0xffffffffu, sc, 4);
        float rd = __shfl_xor_sync(0xffffffffu, sd, 4);
        a[0] = (up ? a[1] : a[0]) + ra;
        b[0] = (up ? b[1] : b[0]) + rb;
        c[0] = (up ? c[1] : c[0]) + rc;
        d[0] = (up ? d[1] : d[0]) + rd;
    }
    a[0] += __shfl_xor_sync(0xffffffffu, a[0], 2);
    b[0] += __shfl_xor_sync(0xffffffffu, b[0], 2);
    c[0] += __shfl_xor_sync(0xffffffffu, c[0], 2);
    d[0] += __shfl_xor_sync(0xffffffffu, d[0], 2);
    a[0] += __shfl_xor_sync(0xffffffffu, a[0], 1);
    b[0] += __shfl_xor_sync(0xffffffffu, b[0], 1);
    c[0] += __shfl_xor_sync(0xffffffffu, c[0], 1);
    d[0] += __shfl_xor_sync(0xffffffffu, d[0], 1);
}

// 4-way softmax over 8-j groups, no max subtraction (scores tiny; exact-safe).
__device__ __forceinline__ void softmax4(float s0, float s1, float s2, float s3,
                                         float& a0, float& a1, float& a2, float& a3) {
    float e0 = __expf(s0), e1 = __expf(s1), e2 = __expf(s2), e3 = __expf(s3);
    float t0 = e0, t1 = e1, t2 = e2, t3 = e3;
    t0 += __shfl_xor_sync(0xffffffffu, t0, 4);
    t1 += __shfl_xor_sync(0xffffffffu, t1, 4);
    t2 += __shfl_xor_sync(0xffffffffu, t2, 4);
    t3 += __shfl_xor_sync(0xffffffffu, t3, 4);
    t0 += __shfl_xor_sync(0xffffffffu, t0, 8);
    t1 += __shfl_xor_sync(0xffffffffu, t1, 8);
    t2 += __shfl_xor_sync(0xffffffffu, t2, 8);
    t3 += __shfl_xor_sync(0xffffffffu, t3, 8);
    t0 += __shfl_xor_sync(0xffffffffu, t0, 16);
    t1 += __shfl_xor_sync(0xffffffffu, t1, 16);
    t2 += __shfl_xor_sync(0xffffffffu, t2, 16);
    t3 += __shfl_xor_sync(0xffffffffu, t3, 16);
    a0 = __fdividef(e0, t0);
    a1 = __fdividef(e1, t1);
    a2 = __fdividef(e2, t2);
    a3 = __fdividef(e3, t3);
}

__global__ __launch_bounds__(64, 8) void decoder_kernel(
    const float* __restrict__ cost_maps,
    const float* __restrict__ cost_memory,
    const float* __restrict__ coords1,
    const float* __restrict__ fte_b1,
    const float* __restrict__ fte_b2,
    const float* __restrict__ ln1_g, const float* __restrict__ ln1_b,
    const float* __restrict__ ln2_g, const float* __restrict__ ln2_b,
    const float* __restrict__ bq,  const float* __restrict__ bv,
    const float* __restrict__ bp,
    const float* __restrict__ fb1, const float* __restrict__ fb2,
    float* __restrict__ out)
{
    __shared__ BlkSmem S;
    const int tid  = threadIdx.x;
    const int warp = tid >> 5;
    const int l    = tid & 31;
    const int o    = tid;               // lane's output dim (0..63)
    const int n0   = blockIdx.x * 4;
    const int b    = n0 >> 12;
    const int pix0 = n0 & 4095;

    float cx[4], cy[4];
    #pragma unroll
    for (int t = 0; t < 4; ++t) {
        cx[t] = coords1[b * 8192 + pix0 + t];
        cy[t] = coords1[b * 8192 + 4096 + pix0 + t];
    }

    // ---- phase 0: load cost_memory into u rows (warp w -> tokens 2w,2w+1) ----
    #pragma unroll
    for (int tt = 0; tt < 2; ++tt) {
        const int t = 2 * warp + tt;
        const float4* src = (const float4*)(cost_memory + (size_t)(n0 + t) * 1024);
        #pragma unroll
        for (int r = 0; r < 8; ++r)
            *(float4*)&S.u[t][r * 132 + 4 * l] = src[r * 32 + l];
    }

    // ---- phase 1: bilinear sampling; warp w handles tokens 2w, 2w+1 ----
    #pragma unroll
    for (int tt = 0; tt < 2; ++tt) {
        const int t = 2 * warp + tt;
        const float* cmap = cost_maps + (size_t)(n0 + t) * 4096;
        for (int ss = l; ss < 81; ss += 32) {
            int si = ss % 9, sj = ss / 9;
            float px = cx[t] + (float)(si - 4);
            float py = cy[t] + (float)(sj - 4);
            float fx0 = floorf(px), fy0 = floorf(py);
            float wx = px - fx0, wy = py - fy0;
            int ix = (int)fx0, iy = (int)fy0;
            float v00 = samp_map(cmap, ix,     iy);
            float v10 = samp_map(cmap, ix + 1, iy);
            float v01 = samp_map(cmap, ix,     iy + 1);
            float v11 = samp_map(cmap, ix + 1, iy + 1);
            S.corr[t][si * 9 + sj] =
                  v00 * (1.f - wx) * (1.f - wy) + v10 * wx * (1.f - wy)
                + v01 * (1.f - wx) * wy         + v11 * wx * wy;
        }
        if (l < 7) S.corr[t][81 + l] = 0.f;
    }
    __syncthreads();

    // ---- phase 2: FTE1 = gelu(corr @ W1 + b1) ----
    {
        float bb = fte_b1[o];
        float r0 = bb, r1 = bb, r2 = bb, r3 = bb;
        mm4s<42>(S.corr[0], S.corr[1], S.corr[2], S.corr[3],
                 g_wpk2 + OFF2_W1, o, r0, r1, r2, r3);
        S.A[0][o] = gelu_exact(r0);
        S.A[1][o] = gelu_exact(r1);
        S.A[2][o] = gelu_exact(r2);
        S.A[3][o] = gelu_exact(r3);
    }
    __syncthreads();

    // ---- phase 3: query = A @ W2 + b2 (= short) ----
    float q[4];
    {
        float bb = fte_b2[o];
        q[0] = bb; q[1] = bb; q[2] = bb; q[3] = bb;
        mm4s<32>(S.A[0], S.A[1], S.A[2], S.A[3],
                 g_wpk2 + OFF2_W2, o, q[0], q[1], q[2], q[3]);
        #pragma unroll
        for (int t = 0; t < 4; ++t) S.sh[t][o] = q[t];
    }

    // ---- phase 4: layernorm1 (cross-warp partials) + positional encoding ----
    {
        float s[4], sq[4];
        #pragma unroll
        for (int t = 0; t < 4; ++t) { s[t] = q[t]; sq[t] = q[t] * q[t]; }
        #pragma unroll
        for (int off = 16; off; off >>= 1) {
            #pragma unroll
            for (int t = 0; t < 4; ++t) {
                s[t]  += __shfl_xor_sync(0xffffffffu, s[t],  off);
                sq[t] += __shfl_xor_sync(0xffffffffu, sq[t], off);
            }
        }
        if (l == 0) {
            #pragma unroll
            for (int t = 0; t < 4; ++t) {
                S.part[warp][t][0] = s[t];
                S.part[warp][t][1] = sq[t];
            }
        }
        __syncthreads();
        float g = ln1_g[o], be = ln1_b[o];
        #pragma unroll
        for (int t = 0; t < 4; ++t) {
            float sum = S.part[0][t][0] + S.part[1][t][0];
            float sqs = S.part[0][t][1] + S.part[1][t][1];
            float mean = sum * (1.f / 64.f);
            float var  = sqs * (1.f / 64.f) - mean * mean;
            float inv  = rsqrtf(var + 1e-5f);
            S.B[t][o] = (q[t] - mean) * inv * g + be + posenc(cx[t], cy[t], o);
        }
    }
    __syncthreads();

    // ---- phase 5: qlin = B @ wq + bq ----
    {
        float bb = bq[o];
        float r0 = bb, r1 = bb, r2 = bb, r3 = bb;
        mm4s<32>(S.B[0], S.B[1], S.B[2], S.B[3],
                 g_wpk2 + OFF2_WQ, o, r0, r1, r2, r3);
        S.qlin[0][o] = r0; S.qlin[1][o] = r1;
        S.qlin[2][o] = r2; S.qlin[3][o] = r3;
    }
    __syncthreads();

    // ---- phases 6-7: scores+softmax, 4-way interleave (h,h+4) x 2 tokens ----
    {
        const int t0 = 2 * warp, t1 = t0 + 1;
        const float4* wk4 = (const float4*)g_wk_t;
        const float scale = 0.35355339059327373f;
        #pragma unroll
        for (int hh = 0; hh < 4; ++hh) {
            const int hA = hh, hB = hh + 4;
            float qA0[8], qA1[8], qB0[8], qB1[8];
            *(float4*)&qA0[0] = *(const float4*)&S.qlin[t0][hA * 8];
            *(float4*)&qA0[4] = *(const float4*)&S.qlin[t0][hA * 8 + 4];
            *(float4*)&qA1[0] = *(const float4*)&S.qlin[t1][hA * 8];
            *(float4*)&qA1[4] = *(const float4*)&S.qlin[t1][hA * 8 + 4];
            *(float4*)&qB0[0] = *(const float4*)&S.qlin[t0][hB * 8];
            *(float4*)&qB0[4] = *(const float4*)&S.qlin[t0][hB * 8 + 4];
            *(float4*)&qB1[0] = *(const float4*)&S.qlin[t1][hB * 8];
            *(float4*)&qB1[4] = *(const float4*)&S.qlin[t1][hB * 8 + 4];
            float4 tfA0 = make_float4(0.f, 0.f, 0.f, 0.f);
            float4 tfA1 = tfA0, tfB0 = tfA0, tfB1 = tfA0;
            #pragma unroll
            for (int e = 0; e < 8; ++e) {
                float4 wA = wk4[(hA * 8 + e) * 32 + l];
                float4 wB = wk4[(hB * 8 + e) * 32 + l];
                tfA0 = fma4(qA0[e], wA, tfA0);
                tfA1 = fma4(qA1[e], wA, tfA1);
                tfB0 = fma4(qB0[e], wB, tfB0);
                tfB1 = fma4(qB1[e], wB, tfB1);
            }
            float vA0[8], vA1[8], vB0[8], vB1[8];
            #pragma unroll
            for (int j = 0; j < 8; ++j) {
                float4 m0 = *(const float4*)&S.u[t0][j * 132 + 4 * l];
                float4 m1 = *(const float4*)&S.u[t1][j * 132 + 4 * l];
                vA0[j] = dot4(tfA0, m0);
                vA1[j] = dot4(tfA1, m1);
                vB0[j] = dot4(tfB0, m0);
                vB1[j] = dot4(tfB1, m1);
            }
            score_reduce4(vA0, vA1, vB0, vB1, l);
            float aA0, aA1, aB0, aB1;
            softmax4(vA0[0] * scale, vA1[0] * scale,
                     vB0[0] * scale, vB1[0] * scale, aA0, aA1, aB0, aB1);
            if ((l & 3) == 0) {
                int jj = (l >> 2) & 7;
                S.attn[t0][hA * 8 + jj] = aA0;
                S.attn[t1][hA * 8 + jj] = aA1;
                S.attn[t0][hB * 8 + jj] = aB0;
                S.attn[t1][hB * 8 + jj] = aB1;
            }
        }
        __syncwarp();

        // ---- phase 8: u[h] = sum_j attn[h][j]*cm[j]; overwrite u in place ----
        #pragma unroll
        for (int tt = 0; tt < 2; ++tt) {
            const int t = t0 + tt;
            float4 cmf[8];
            #pragma unroll
            for (int j = 0; j < 8; ++j)
                cmf[j] = *(const float4*)&S.u[t][j * 132 + 4 * l];
            float4 ua[8];
            #pragma unroll
            for (int h = 0; h < 8; ++h) ua[h] = make_float4(0.f, 0.f, 0.f, 0.f);
            #pragma unroll
            for (int j = 0; j < 8; ++j) {
                float4 m = cmf[j];
                #pragma unroll
                for (int h = 0; h < 8; ++h)
                    ua[h] = fma4(S.attn[t][h * 8 + j], m, ua[h]);
            }
            #pragma unroll
            for (int h = 0; h < 8; ++h)
                *(float4*)&S.u[t][h * 132 + 4 * l] = ua[h];
        }
    }
    __syncthreads();

    // ---- phase 9: out = u @ wv + bv  (per-lane head row of u) ----
    {
        float bb = bv[o];
        float r0 = bb, r1 = bb, r2 = bb, r3 = bb;
        const int h = o >> 3;
        mm4s<64>(&S.u[0][h * 132], &S.u[1][h * 132],
                 &S.u[2][h * 132], &S.u[3][h * 132],
                 g_wpk2 + OFF2_WV, o, r0, r1, r2, r3);
        S.A[0][o] = r0; S.A[1][o] = r1; S.A[2][o] = r2; S.A[3][o] = r3;
    }
    __syncthreads();

    // ---- phase 10: x = concat(out, short) @ wp + bp + short ----
    float x[4];
    {
        float bb = bp[o];
        x[0] = bb; x[1] = bb; x[2] = bb; x[3] = bb;
        mm4s<32>(S.A[0], S.A[1], S.A[2], S.A[3],
                 g_wpk2 + OFF2_WP1, o, x[0], x[1], x[2], x[3]);
        mm4s<32>(S.sh[0], S.sh[1], S.sh[2], S.sh[3],
                 g_wpk2 + OFF2_WP2, o, x[0], x[1], x[2], x[3]);
        #pragma unroll
        for (int t = 0; t < 4; ++t) x[t] += S.sh[t][o];
    }

    // ---- phase 11: layernorm2 (cross-warp partials) ----
    {
        float s[4], sq[4];
        #pragma unroll
        for (int t = 0; t < 4; ++t) { s[t] = x[t]; sq[t] = x[t] * x[t]; }
        #pragma unroll
        for (int off = 16; off; off >>= 1) {
            #pragma unroll
            for (int t = 0; t < 4; ++t) {
                s[t]  += __shfl_xor_sync(0xffffffffu, s[t],  off);
                sq[t] += __shfl_xor_sync(0xffffffffu, sq[t], off);
            }
        }
        if (l == 0) {
            #pragma unroll
            for (int t = 0; t < 4; ++t) {
                S.part[warp][t][0] = s[t];
                S.part[warp][t][1] = sq[t];
            }
        }
        __syncthreads();
        float g = ln2_g[o], be = ln2_b[o];
        #pragma unroll
        for (int t = 0; t < 4; ++t) {
            float sum = S.part[0][t][0] + S.part[1][t][0];
            float sqs = S.part[0][t][1] + S.part[1][t][1];
            float mean = sum * (1.f / 64.f);
            float var  = sqs * (1.f / 64.f) - mean * mean;
            float inv  = rsqrtf(var + 1e-5f);
            S.B[t][o] = (x[t] - mean) * inv * g + be;
        }
    }
    __syncthreads();

    // ---- phase 12: FFN hidden ----
    {
        float bb = fb1[o];
        float r0 = bb, r1 = bb, r2 = bb, r3 = bb;
        mm4s<32>(S.B[0], S.B[1], S.B[2], S.B[3],
                 g_wpk2 + OFF2_F1, o, r0, r1, r2, r3);
        S.A[0][o] = gelu_exact(r0);
        S.A[1][o] = gelu_exact(r1);
        S.A[2][o] = gelu_exact(r2);
        S.A[3][o] = gelu_exact(r3);
    }
    __syncthreads();

    // ---- phase 13: FFN out + residual ----
    {
        float bb = fb2[o];
        float r0 = bb, r1 = bb, r2 = bb, r3 = bb;
        mm4s<32>(S.A[0], S.A[1], S.A[2], S.A[3],
                 g_wpk2 + OFF2_F2, o, r0, r1, r2, r3);
        S.xs[0][o] = x[0] + r0;
        S.xs[1][o] = x[1] + r1;
        S.xs[2][o] = x[2] + r2;
        S.xs[3][o] = x[3] + r3;
    }
    __syncthreads();

    // ---- phase 14: transposed writeout, STG.128 of 4 token values ----
    {
        float* cg = out + FLOW_SZ + (size_t)b * 64 * 4096 + pix0;
        float4 v = make_float4(S.xs[0][o], S.xs[1][o], S.xs[2][o], S.xs[3][o]);
        *(float4*)(cg + (size_t)o * 4096) = v;
    }
}

// ============================================================================
// Convex upsampling, 16 pixels per block. Blocks 0..74 pack g_wpk2;
// blocks 75..106 transpose wk into g_wk_t.
// ============================================================================
__global__ __launch_bounds__(256) void upsample_kernel(
    const float* __restrict__ coords1,
    const float* __restrict__ up_mask,
    const float* __restrict__ fte_w1,
    const float* __restrict__ fte_w2,
    const float* __restrict__ wq,
    const float* __restrict__ wk,
    const float* __restrict__ wv,
    const float* __restrict__ wp,
    const float* __restrict__ fw1,
    const float* __restrict__ fw2,
    float* __restrict__ out)
{
    extern __shared__ float dyn[];
    const int PAD = 20;
    float* slab = dyn;             // 576 * PAD
    float* fl   = dyn + 576 * PAD; // 2 * 3 * 18

    int blk = blockIdx.x;
    int tid = threadIdx.x;

    if (blk < 75) {
        int i = blk * 256 + tid;
        if (i < WPK2_TOTAL) {
            int pr = i >> 6, o = i & 63;
            float2 v;
            if (pr < 42) {
                int c = 2 * pr;
                v.x = (c < 81)     ? fte_w1[o * 81 + c]     : 0.f;
                v.y = (c + 1 < 81) ? fte_w1[o * 81 + c + 1] : 0.f;
            } else if (pr < 74) {
                int c = 2 * (pr - 42);
                v = make_float2(fte_w2[o * 64 + c], fte_w2[o * 64 + c + 1]);
            } else if (pr < 106) {
                int c = 2 * (pr - 74);
                v = make_float2(wq[c * 64 + o], wq[(c + 1) * 64 + o]);
            } else if (pr < 170) {
                int c = 2 * (pr - 106);
                v = make_float2(wv[c * 64 + o], wv[(c + 1) * 64 + o]);
            } else if (pr < 234) {
                int c = 2 * (pr - 170);
                v = make_float2(wp[c * 64 + o], wp[(c + 1) * 64 + o]);
            } else if (pr < 266) {
                int c = 2 * (pr - 234);
                v = make_float2(fw1[c * 64 + o], fw1[(c + 1) * 64 + o]);
            } else {
                int c = 2 * (pr - 266);
                v = make_float2(fw2[c * 64 + o], fw2[(c + 1) * 64 + o]);
            }
            g_wpk2[i] = v;
        }
    } else if (blk < 107) {
        int i = (blk - 75) * 256 + tid;
        int d = i >> 7, c = i & 127;
        g_wk_t[i] = wk[c * 64 + d];
    }

    const int b  = blk >> 8;
    const int r2 = blk & 255;
    const int y  = r2 >> 2;
    const int x0 = (r2 & 3) << 4;

    const float* mbase = up_mask + (size_t)b * 576 * 4096 + y * 64 + x0;
    for (int idx = tid; idx < 576 * 4; idx += 256) {
        int ch = idx >> 2, k = idx & 3;
        *(float4*)&slab[ch * PAD + 4 * k] =
            *(const float4*)(mbase + (size_t)ch * 4096 + 4 * k);
    }
    for (int idx = tid; idx < 2 * 3 * 18; idx += 256) {
        int c = idx / 54, rr = idx % 54, r = rr / 18, cc = rr % 18;
        int yy = y + r - 1, xx = x0 + cc - 1;
        float v = 0.0f;
        if ((unsigned)yy < 64u && (unsigned)xx < 64u) {
            float coord = coords1[b * 8192 + c * 4096 + yy * 64 + xx];
            v = 8.0f * (coord - (float)(c == 0 ? xx : yy));
        }
        fl[c * 54 + r * 18 + cc] = v;
    }
    __syncthreads();

    float* ob0 = out + (size_t)b * 2 * 512 * 512 + (size_t)(8 * y) * 512 + x0 * 8;
    for (int it = 0; it < 4; ++it) {
        int site = it * 256 + tid;
        int i = site >> 7;
        int rr = site & 127;
        int p = rr >> 3, j = rr & 7;
        int ij = i * 8 + j;
        float w[9];
        float s = 0.f;
        #pragma unroll
        for (int kk = 0; kk < 9; ++kk) {
            w[kk] = __expf(slab[(kk * 64 + ij) * PAD + p]);
            s += w[kk];
        }
        float inv = __fdividef(1.0f, s);
        float u0 = 0.f, u1 = 0.f;
        #pragma unroll
        for (int kk = 0; kk < 9; ++kk) {
            int dy = kk / 3, dx = kk - dy * 3;
            u0 = fmaf(w[kk], fl[0 * 54 + dy * 18 + p + dx], u0);
            u1 = fmaf(w[kk], fl[1 * 54 + dy * 18 + p + dx], u1);
        }
        float* oo = ob0 + (size_t)i * 512 + p * 8 + j;
        oo[0] = u0 * inv;
        oo[512 * 512] = u1 * inv;
    }
}

extern "C" void kernel_launch(void* const* d_in, const int* in_sizes, int n_in,
                              void* d_out, int out_size) {
    const float* cost_maps   = (const float*)d_in[0];
    const float* cost_memory = (const float*)d_in[1];
    const float* coords1     = (const float*)d_in[2];
    const float* up_mask     = (const float*)d_in[3];
    const float* fte_w1      = (const float*)d_in[4];
    const float* fte_b1      = (const float*)d_in[5];
    const float* fte_w2      = (const float*)d_in[6];
    const float* fte_b2      = (const float*)d_in[7];
    const float* ln1_g       = (const float*)d_in[8];
    const float* ln1_b       = (const float*)d_in[9];
    const float* ln2_g       = (const float*)d_in[10];
    const float* ln2_b       = (const float*)d_in[11];
    const float* wq          = (const float*)d_in[12];
    const float* bq          = (const float*)d_in[13];
    const float* wk          = (const float*)d_in[14];
    const float* wv          = (const float*)d_in[16];
    const float* bv          = (const float*)d_in[17];
    const float* wp          = (const float*)d_in[18];
    const float* bp          = (const float*)d_in[19];
    const float* fw1         = (const float*)d_in[20];
    const float* fb1         = (const float*)d_in[21];
    const float* fw2         = (const float*)d_in[22];
    const float* fb2         = (const float*)d_in[23];
    float* out = (float*)d_out;

    const int smem_bytes = (576 * 20 + 2 * 3 * 18) * 4;   // 46,512 B
    cudaFuncSetAttribute(upsample_kernel,
                         cudaFuncAttributeMaxDynamicSharedMemorySize, smem_bytes);

    upsample_kernel<<<512, 256, smem_bytes>>>(coords1, up_mask, fte_w1, fte_w2,
                                              wq, wk, wv, wp, fw1, fw2, out);
    decoder_kernel<<<2048, 64>>>(cost_maps, cost_memory, coords1,
                                 fte_b1, fte_b2,
                                 ln1_g, ln1_b, ln2_g, ln2_b,
                                 bq, bv, bp, fb1, fb2, out);
}